// round 13
// baseline (speedup 1.0000x reference)
#include <cuda_runtime.h>
#include <cuda_bf16.h>
#include <math.h>

#define N_NODES 50000
#define N_EDGES 800000
#define NINP 128
#define NE 32
#define KSUP 8
#define NOUT1 128
#define NOUT2 64
#define OUTC 192
#define NHALF 25088   // chunk boundary (multiple of 128)

// ---------------- device scratch ---------------------------------------------
__device__ float g_e[(size_t)N_EDGES * KSUP];             // edge feats, EDGE order
__device__ int   g_deg[N_NODES];
__device__ int   g_off[N_NODES + 1];
__device__ int   g_cur[N_NODES];
__device__ int   g_eid[N_EDGES];                          // CSR slot -> edge id
__device__ int   g_src[N_EDGES];                          // CSR slot -> src node
__device__ int   g_part[64];
__device__ __nv_bfloat16 g_Hh[(size_t)(N_NODES + 128) * KSUP * NINP]; // H hi
__device__ __nv_bfloat16 g_Hl[(size_t)(N_NODES + 128) * KSUP * NINP]; // H lo
__device__ __nv_bfloat16 g_Wkh[KSUP * NINP * NOUT1];      // TRANSPOSED [n][k]
__device__ __nv_bfloat16 g_Wkl[KSUP * NINP * NOUT1];      // TRANSPOSED [n][k]
__device__ int   g_is64;

// ---------------- zero-MUFU exp2 / tanh-product ------------------------------
__device__ __forceinline__ float exp2k(float a) {   // ~= e^{2a}
    float y = fminf(fmaxf(a * 2.885390081777927f, -28.f), 28.f);
    float n = rintf(y);
    float f = y - n;
    float p = 1.3333558e-3f;
    p = fmaf(p, f, 9.6181291e-3f);
    p = fmaf(p, f, 5.5504109e-2f);
    p = fmaf(p, f, 2.4022651e-1f);
    p = fmaf(p, f, 6.9314718e-1f);
    p = fmaf(p, f, 1.0f);
    return __int_as_float(__float_as_int(p) + (((int)n) << 23));
}
__device__ __forceinline__ float tanh_prod(float a, float b) { // tanh(a)*tanh(b)
    float za = exp2k(a), zb = exp2k(b);
    float num = (za - 1.f) * (zb - 1.f);
    float den = (za + 1.f) * (zb + 1.f);
    float r = __int_as_float(0x7EF311C3 - __float_as_int(den));
    r = r * fmaf(-den, r, 2.f);
    r = r * fmaf(-den, r, 2.f);
    return num * r;
}

__device__ __forceinline__ int load_idx(const void* ei, long long pos, int is64) {
    if (is64) return (int)((const long long*)ei)[pos];
    return ((const int*)ei)[pos];
}

// ---------------- cp.async helpers -------------------------------------------
__device__ __forceinline__ void cp16(void* dst_smem, const void* src) {
    unsigned d = (unsigned)__cvta_generic_to_shared(dst_smem);
    asm volatile("cp.async.cg.shared.global [%0], [%1], 16;" :: "r"(d), "l"(src));
}
#define CP_COMMIT() asm volatile("cp.async.commit_group;" ::: "memory")
#define CP_WAIT1()  asm volatile("cp.async.wait_group 1;" ::: "memory")
#define CP_WAIT0()  asm volatile("cp.async.wait_group 0;" ::: "memory")

// ---------------- detect idx dtype + zero deg --------------------------------
__global__ void detect_zero_kernel(const unsigned int* __restrict__ ei) {
    int i = blockIdx.x * blockDim.x + threadIdx.x;
    if (i < N_NODES) g_deg[i] = 0;
    if (blockIdx.x == 0 && threadIdx.x == 0) {
        int is64 = 1;
        for (int k = 0; k < 128; k++)
            if (ei[2 * k + 1] != 0u) { is64 = 0; break; }
        g_is64 = is64;
    }
}

// ---------------- CSR build --------------------------------------------------
__global__ void hist_kernel(const void* __restrict__ ei) {
    int e = blockIdx.x * blockDim.x + threadIdx.x;
    if (e >= N_EDGES) return;
    int dst = load_idx(ei, (long long)N_EDGES + e, g_is64);
    atomicAdd(&g_deg[dst], 1);
}

__global__ void scan_partial_kernel() {
    __shared__ int s[1024];
    int i = blockIdx.x * 1024 + threadIdx.x;
    s[threadIdx.x] = (i < N_NODES) ? g_deg[i] : 0;
    __syncthreads();
    for (int d = 512; d > 0; d >>= 1) {
        if (threadIdx.x < d) s[threadIdx.x] += s[threadIdx.x + d];
        __syncthreads();
    }
    if (threadIdx.x == 0) g_part[blockIdx.x] = s[0];
}

__global__ void scan_apply_kernel() {
    __shared__ int sp[64];
    __shared__ int s[1024];
    int tid = threadIdx.x;
    int nblk = gridDim.x;
    if (tid == 0) {
        int run = 0;
        for (int i = 0; i < nblk; i++) { int t = g_part[i]; sp[i] = run; run += t; }
    }
    __syncthreads();
    int base = sp[blockIdx.x];
    int i = blockIdx.x * 1024 + tid;
    int v = (i < N_NODES) ? g_deg[i] : 0;
    s[tid] = v;
    __syncthreads();
    for (int d = 1; d < 1024; d <<= 1) {
        int t = (tid >= d) ? s[tid - d] : 0;
        __syncthreads();
        s[tid] += t;
        __syncthreads();
    }
    int incl = base + s[tid];
    if (i < N_NODES) { g_off[i + 1] = incl; g_cur[i] = incl - v; }
    if (blockIdx.x == 0 && tid == 0) g_off[0] = 0;
}

__global__ void scatter_kernel(const void* __restrict__ ei) {
    int e = blockIdx.x * blockDim.x + threadIdx.x;
    if (e >= N_EDGES) return;
    int is64 = g_is64;
    int dst = load_idx(ei, (long long)N_EDGES + e, is64);
    int src = load_idx(ei, e, is64);
    int p = atomicAdd(&g_cur[dst], 1);
    g_eid[p] = e;
    g_src[p] = src;
}

// ---------------- bf16-split mma helper --------------------------------------
__device__ __forceinline__ void mma_bf16(float* d, unsigned a0, unsigned a1,
                                         unsigned a2, unsigned a3,
                                         unsigned b0, unsigned b1) {
    asm volatile(
        "mma.sync.aligned.m16n8k16.row.col.f32.bf16.bf16.f32 "
        "{%0,%1,%2,%3},{%4,%5,%6,%7},{%8,%9},{%0,%1,%2,%3};"
        : "+f"(d[0]), "+f"(d[1]), "+f"(d[2]), "+f"(d[3])
        : "r"(a0), "r"(a1), "r"(a2), "r"(a3), "r"(b0), "r"(b1));
}

__device__ __forceinline__ void pack_hl(float x, float y, unsigned& hi, unsigned& lo) {
    __nv_bfloat16 hx = __float2bfloat16(x), hy = __float2bfloat16(y);
    __nv_bfloat162 hp; hp.x = hx; hp.y = hy;
    hi = *(unsigned*)&hp;
    __nv_bfloat162 lp;
    lp.x = __float2bfloat16(x - __bfloat162float(hx));
    lp.y = __float2bfloat16(y - __bfloat162float(hy));
    lo = *(unsigned*)&lp;
}

// ---------------- Wk hi/lo precompute (TRANSPOSED) ---------------------------
__global__ void wk_convert_kernel(const float* __restrict__ Wk) {
    int i = blockIdx.x * 256 + threadIdx.x;   // 131072 total
    int k = i >> 7, n = i & 127;
    float v = Wk[i];
    __nv_bfloat16 h = __float2bfloat16(v);
    g_Wkh[(size_t)n * 1024 + k] = h;
    g_Wkl[(size_t)n * 1024 + k] = __float2bfloat16(v - __bfloat162float(h));
}

// ---------------- edge MLP via tensor cores (edge-order output) --------------
#define EW_SMEM 55552
#define ECHUNKS 5
__global__ void __launch_bounds__(256, 3) edge_mma_kernel(
        const float* __restrict__ ea, const float* __restrict__ W1,
        const float* __restrict__ W2, const float* __restrict__ W3,
        const float* __restrict__ W4) {
    extern __shared__ char sbuf[];
    __nv_bfloat16* Bh  = (__nv_bfloat16*)sbuf;             // [192][40]
    __nv_bfloat16* Bl  = (__nv_bfloat16*)(sbuf + 15360);
    __nv_bfloat16* W4h = (__nv_bfloat16*)(sbuf + 30720);   // [8 cols][136 k]
    __nv_bfloat16* W4l = (__nv_bfloat16*)(sbuf + 32896);
    __nv_bfloat16* Ah  = (__nv_bfloat16*)(sbuf + 35072);   // [128][40]
    __nv_bfloat16* Al  = (__nv_bfloat16*)(sbuf + 45312);

    int tid = threadIdx.x;
    int lane = tid & 31, w = tid >> 5;
    int g = lane >> 2, c2 = (lane & 3) * 2;

    for (int idx = tid; idx < 6144; idx += 256) {
        int n = idx >> 5, k = idx & 31;
        int s = n >> 6, j = n & 63;
        const float* Wp = (s == 0) ? W1 : (s == 1) ? W2 : W3;
        float v = Wp[k * 64 + j];
        __nv_bfloat16 h = __float2bfloat16(v);
        Bh[n * 40 + k] = h;
        Bl[n * 40 + k] = __float2bfloat16(v - __bfloat162float(h));
    }
    for (int idx = tid; idx < 1024; idx += 256) {
        int kk = idx >> 3, c = idx & 7;
        float v = W4[idx];
        __nv_bfloat16 h = __float2bfloat16(v);
        W4h[c * 136 + kk] = h;
        W4l[c * 136 + kk] = __float2bfloat16(v - __bfloat162float(h));
    }

    for (int ch = 0; ch < ECHUNKS; ch++) {
        long long eBase = ((long long)blockIdx.x * ECHUNKS + ch) * 128;
        __syncthreads();
#pragma unroll
        for (int i = 0; i < 4; i++) {
            int idx = tid + i * 256;
            int r = idx >> 3, q = (idx & 7) * 4;
            float4 v = *(const float4*)(ea + (eBase + r) * NE + q);
            unsigned h0, l0, h1, l1;
            pack_hl(v.x, v.y, h0, l0);
            pack_hl(v.z, v.w, h1, l1);
            *(unsigned*)&Ah[r * 40 + q]     = h0;
            *(unsigned*)&Ah[r * 40 + q + 2] = h1;
            *(unsigned*)&Al[r * 40 + q]     = l0;
            *(unsigned*)&Al[r * 40 + q + 2] = l1;
        }
        __syncthreads();

        int m0 = w * 16 + g;
        unsigned ah[2][4], al[2][4];
#pragma unroll
        for (int kc = 0; kc < 2; kc++) {
            int kb = kc * 16 + c2;
            ah[kc][0] = *(unsigned*)&Ah[m0 * 40 + kb];
            ah[kc][1] = *(unsigned*)&Ah[(m0 + 8) * 40 + kb];
            ah[kc][2] = *(unsigned*)&Ah[m0 * 40 + kb + 8];
            ah[kc][3] = *(unsigned*)&Ah[(m0 + 8) * 40 + kb + 8];
            al[kc][0] = *(unsigned*)&Al[m0 * 40 + kb];
            al[kc][1] = *(unsigned*)&Al[(m0 + 8) * 40 + kb];
            al[kc][2] = *(unsigned*)&Al[m0 * 40 + kb + 8];
            al[kc][3] = *(unsigned*)&Al[(m0 + 8) * 40 + kb + 8];
        }

        float o[4] = {0.f, 0.f, 0.f, 0.f};
#pragma unroll
        for (int jp = 0; jp < 4; jp++) {
            int ko = jp * 16;
            unsigned linH[4], linL[4], mulH[4], mulL[4];
#pragma unroll
            for (int sub = 0; sub < 2; sub++) {
                int j = ko + sub * 8;
                float lin[4] = {0.f, 0.f, 0.f, 0.f};
                float t2[4]  = {0.f, 0.f, 0.f, 0.f};
                float t3[4]  = {0.f, 0.f, 0.f, 0.f};
#pragma unroll
                for (int kc = 0; kc < 2; kc++) {
                    int kb = kc * 16 + c2;
                    {
                        int n = j + g;
                        unsigned bh0 = *(unsigned*)&Bh[n * 40 + kb];
                        unsigned bh1 = *(unsigned*)&Bh[n * 40 + kb + 8];
                        unsigned bl0 = *(unsigned*)&Bl[n * 40 + kb];
                        unsigned bl1 = *(unsigned*)&Bl[n * 40 + kb + 8];
                        mma_bf16(lin, ah[kc][0], ah[kc][1], ah[kc][2], ah[kc][3], bh0, bh1);
                        mma_bf16(lin, ah[kc][0], ah[kc][1], ah[kc][2], ah[kc][3], bl0, bl1);
                        mma_bf16(lin, al[kc][0], al[kc][1], al[kc][2], al[kc][3], bh0, bh1);
                    }
                    {
                        int n = 64 + j + g;
                        unsigned bh0 = *(unsigned*)&Bh[n * 40 + kb];
                        unsigned bh1 = *(unsigned*)&Bh[n * 40 + kb + 8];
                        unsigned bl0 = *(unsigned*)&Bl[n * 40 + kb];
                        unsigned bl1 = *(unsigned*)&Bl[n * 40 + kb + 8];
                        mma_bf16(t2, ah[kc][0], ah[kc][1], ah[kc][2], ah[kc][3], bh0, bh1);
                        mma_bf16(t2, ah[kc][0], ah[kc][1], ah[kc][2], ah[kc][3], bl0, bl1);
                        mma_bf16(t2, al[kc][0], al[kc][1], al[kc][2], al[kc][3], bh0, bh1);
                    }
                    {
                        int n = 128 + j + g;
                        unsigned bh0 = *(unsigned*)&Bh[n * 40 + kb];
                        unsigned bh1 = *(unsigned*)&Bh[n * 40 + kb + 8];
                        unsigned bl0 = *(unsigned*)&Bl[n * 40 + kb];
                        unsigned bl1 = *(unsigned*)&Bl[n * 40 + kb + 8];
                        mma_bf16(t3, ah[kc][0], ah[kc][1], ah[kc][2], ah[kc][3], bh0, bh1);
                        mma_bf16(t3, ah[kc][0], ah[kc][1], ah[kc][2], ah[kc][3], bl0, bl1);
                        mma_bf16(t3, al[kc][0], al[kc][1], al[kc][2], al[kc][3], bh0, bh1);
                    }
                }
                float lv0 = fmaxf(lin[0], 0.f), lv1 = fmaxf(lin[1], 0.f);
                float lv2 = fmaxf(lin[2], 0.f), lv3 = fmaxf(lin[3], 0.f);
                float mv0 = tanh_prod(t2[0], t3[0]), mv1 = tanh_prod(t2[1], t3[1]);
                float mv2 = tanh_prod(t2[2], t3[2]), mv3 = tanh_prod(t2[3], t3[3]);
                pack_hl(lv0, lv1, linH[sub * 2],     linL[sub * 2]);
                pack_hl(lv2, lv3, linH[sub * 2 + 1], linL[sub * 2 + 1]);
                pack_hl(mv0, mv1, mulH[sub * 2],     mulL[sub * 2]);
                pack_hl(mv2, mv3, mulH[sub * 2 + 1], mulL[sub * 2 + 1]);
            }
            {
                int kb = ko + c2;
                unsigned b0h = *(unsigned*)&W4h[g * 136 + kb];
                unsigned b1h = *(unsigned*)&W4h[g * 136 + kb + 8];
                unsigned b0l = *(unsigned*)&W4l[g * 136 + kb];
                unsigned b1l = *(unsigned*)&W4l[g * 136 + kb + 8];
                mma_bf16(o, linH[0], linH[1], linH[2], linH[3], b0h, b1h);
                mma_bf16(o, linH[0], linH[1], linH[2], linH[3], b0l, b1l);
                mma_bf16(o, linL[0], linL[1], linL[2], linL[3], b0h, b1h);
            }
            {
                int kb = 64 + ko + c2;
                unsigned b0h = *(unsigned*)&W4h[g * 136 + kb];
                unsigned b1h = *(unsigned*)&W4h[g * 136 + kb + 8];
                unsigned b0l = *(unsigned*)&W4l[g * 136 + kb];
                unsigned b1l = *(unsigned*)&W4l[g * 136 + kb + 8];
                mma_bf16(o, mulH[0], mulH[1], mulH[2], mulH[3], b0h, b1h);
                mma_bf16(o, mulH[0], mulH[1], mulH[2], mulH[3], b0l, b1l);
                mma_bf16(o, mulL[0], mulL[1], mulL[2], mulL[3], b0h, b1h);
            }
        }
        long long e0 = eBase + w * 16 + g;
        *(float2*)&g_e[e0 * 8 + c2] =
            make_float2(fmaxf(o[0], 0.f), fmaxf(o[1], 0.f));
        *(float2*)&g_e[(e0 + 8) * 8 + c2] =
            make_float2(fmaxf(o[2], 0.f), fmaxf(o[3], 0.f));
    }
}

// ---------------- per-node aggregation (2 warps per node, node range) --------
__global__ void aggregate_kernel(const float* __restrict__ x,
                                 int nodeStart, int nodeEnd) {
    int gw = (blockIdx.x * blockDim.x + threadIdx.x) >> 5;
    int node = nodeStart + (gw >> 1);
    if (node >= nodeEnd) return;
    int half = gw & 1;
    int lane = threadIdx.x & 31;
    int cbase = half * 64 + lane * 2;

    float acc[8][2];
#pragma unroll
    for (int k = 0; k < 8; k++) { acc[k][0] = 0.f; acc[k][1] = 0.f; }

    int s = g_off[node], t = g_off[node + 1];
    int p = s;
    for (; p + 1 < t; p += 2) {
        int e0i = g_eid[p], e1i = g_eid[p + 1];
        int src0 = g_src[p], src1 = g_src[p + 1];
        float2 xv0 = *(const float2*)(x + (size_t)src0 * NINP + cbase);
        float2 xv1 = *(const float2*)(x + (size_t)src1 * NINP + cbase);
        const float4* ep0 = (const float4*)(g_e + (size_t)e0i * 8);
        const float4* ep1 = (const float4*)(g_e + (size_t)e1i * 8);
        float4 a0 = ep0[0], a1 = ep0[1], b0 = ep1[0], b1 = ep1[1];
        float ek0[8] = {a0.x, a0.y, a0.z, a0.w, a1.x, a1.y, a1.z, a1.w};
        float ek1[8] = {b0.x, b0.y, b0.z, b0.w, b1.x, b1.y, b1.z, b1.w};
#pragma unroll
        for (int k = 0; k < 8; k++) {
            acc[k][0] = fmaf(ek0[k], xv0.x, acc[k][0]);
            acc[k][1] = fmaf(ek0[k], xv0.y, acc[k][1]);
            acc[k][0] = fmaf(ek1[k], xv1.x, acc[k][0]);
            acc[k][1] = fmaf(ek1[k], xv1.y, acc[k][1]);
        }
    }
    if (p < t) {
        int e0i = g_eid[p];
        int src0 = g_src[p];
        float2 xv0 = *(const float2*)(x + (size_t)src0 * NINP + cbase);
        const float4* ep0 = (const float4*)(g_e + (size_t)e0i * 8);
        float4 a0 = ep0[0], a1 = ep0[1];
        float ek0[8] = {a0.x, a0.y, a0.z, a0.w, a1.x, a1.y, a1.z, a1.w};
#pragma unroll
        for (int k = 0; k < 8; k++) {
            acc[k][0] = fmaf(ek0[k], xv0.x, acc[k][0]);
            acc[k][1] = fmaf(ek0[k], xv0.y, acc[k][1]);
        }
    }
    size_t base = (size_t)node * (KSUP * NINP) + cbase;
#pragma unroll
    for (int k = 0; k < 8; k++) {
        unsigned hi, lo;
        pack_hl(acc[k][0], acc[k][1], hi, lo);
        *(unsigned*)&g_Hh[base + k * NINP] = hi;
        *(unsigned*)&g_Hl[base + k * NINP] = lo;
    }
}

// ---------------- spectral GEMM: cp.async double-buffered bf16 mma -----------
#define SP_SMEM 81920
__global__ void __launch_bounds__(256) spectral_mma_kernel(
        const float* __restrict__ bk, float* __restrict__ out, int mStart) {
    extern __shared__ __nv_bfloat16 sm[];
    __nv_bfloat16* Ah = sm;               // 2 x 10240 B
    __nv_bfloat16* Al = sm + 10240;
    __nv_bfloat16* Bh = sm + 20480;
    __nv_bfloat16* Bl = sm + 30720;

    int tid  = threadIdx.x;
    int lane = tid & 31;
    int w    = tid >> 5;
    int wm   = (w & 3) * 32;
    int wn   = (w >> 2) * 64;
    int g    = lane >> 2;
    int c2   = (lane & 3) * 2;
    int mBase = mStart + blockIdx.x * 128;

    float acc[2][8][4];
#pragma unroll
    for (int mt = 0; mt < 2; mt++)
#pragma unroll
        for (int nt = 0; nt < 8; nt++)
#pragma unroll
            for (int qq = 0; qq < 4; qq++) acc[mt][nt][qq] = 0.f;

    auto stage = [&](int s, int kc) {
        int o = s * 5120;
#pragma unroll
        for (int i = 0; i < 2; i++) {
            int idx = tid + i * 256;
            int row = idx >> 2, q = (idx & 3) * 8;
            size_t ga = (size_t)(mBase + row) * 1024 + kc + q;
            cp16(&Ah[o + row * 40 + q], g_Hh + ga);
            cp16(&Al[o + row * 40 + q], g_Hl + ga);
            size_t wa = (size_t)row * 1024 + kc + q;
            cp16(&Bh[o + row * 40 + q], g_Wkh + wa);
            cp16(&Bl[o + row * 40 + q], g_Wkl + wa);
        }
    };

    stage(0, 0);
    CP_COMMIT();

    for (int c = 0; c < 32; c++) {
        int cur = c & 1;
        if (c + 1 < 32) {
            stage((c + 1) & 1, (c + 1) * 32);
            CP_COMMIT();
            CP_WAIT1();
        } else {
            CP_WAIT0();
        }
        __syncthreads();

        int ob = cur * 5120;
#pragma unroll
        for (int ks = 0; ks < 2; ks++) {
            int ko = ks * 16;
            unsigned ah[2][4], al[2][4];
#pragma unroll
            for (int mt = 0; mt < 2; mt++) {
                int r0 = (wm + mt * 16 + g) * 40 + ob + ko + c2;
                ah[mt][0] = *(const unsigned*)&Ah[r0];
                ah[mt][1] = *(const unsigned*)&Ah[r0 + 8 * 40];
                ah[mt][2] = *(const unsigned*)&Ah[r0 + 8];
                ah[mt][3] = *(const unsigned*)&Ah[r0 + 8 * 40 + 8];
                al[mt][0] = *(const unsigned*)&Al[r0];
                al[mt][1] = *(const unsigned*)&Al[r0 + 8 * 40];
                al[mt][2] = *(const unsigned*)&Al[r0 + 8];
                al[mt][3] = *(const unsigned*)&Al[r0 + 8 * 40 + 8];
            }
#pragma unroll
            for (int nt = 0; nt < 8; nt++) {
                int n0 = (wn + nt * 8 + g) * 40 + ob + ko + c2;
                unsigned bh0 = *(const unsigned*)&Bh[n0];
                unsigned bh1 = *(const unsigned*)&Bh[n0 + 8];
                unsigned bl0 = *(const unsigned*)&Bl[n0];
                unsigned bl1 = *(const unsigned*)&Bl[n0 + 8];
#pragma unroll
                for (int mt = 0; mt < 2; mt++) {
                    mma_bf16(acc[mt][nt], ah[mt][0], ah[mt][1], ah[mt][2], ah[mt][3], bh0, bh1);
                    mma_bf16(acc[mt][nt], ah[mt][0], ah[mt][1], ah[mt][2], ah[mt][3], bl0, bl1);
                    mma_bf16(acc[mt][nt], al[mt][0], al[mt][1], al[mt][2], al[mt][3], bh0, bh1);
                }
            }
        }
        __syncthreads();
    }

#pragma unroll
    for (int mt = 0; mt < 2; mt++) {
        int row0 = mBase + wm + mt * 16 + g;
        int row1 = row0 + 8;
#pragma unroll
        for (int nt = 0; nt < 8; nt++) {
            int col = wn + nt * 8 + c2;
            float bx = bk[col], by = bk[col + 1];
            if (row0 < N_NODES) {
                float2 v = make_float2(fmaxf(acc[mt][nt][0] + bx, 0.f),
                                       fmaxf(acc[mt][nt][1] + by, 0.f));
                *(float2*)(out + (size_t)row0 * OUTC + col) = v;
            }
            if (row1 < N_NODES) {
                float2 v = make_float2(fmaxf(acc[mt][nt][2] + bx, 0.f),
                                       fmaxf(acc[mt][nt][3] + by, 0.f));
                *(float2*)(out + (size_t)row1 * OUTC + col) = v;
            }
        }
    }
}

// ---------------- elementwise branch -----------------------------------------
#define EBM 64
#define EBK 32
__global__ void elem_kernel(const float* __restrict__ x,
                            const float* __restrict__ W11,
                            const float* __restrict__ b11,
                            const float* __restrict__ W12,
                            const float* __restrict__ b12,
                            float* __restrict__ out) {
    __shared__ float Xs[EBM][36];
    __shared__ float B1s[EBK][64];
    __shared__ float B2s[EBK][64];
    int tid = threadIdx.x;
    int tx = tid & 15;
    int ty = tid >> 4;
    int mBase = blockIdx.x * EBM;

    float a1[4][4], a2[4][4];
#pragma unroll
    for (int i = 0; i < 4; i++)
#pragma unroll
        for (int j = 0; j < 4; j++) { a1[i][j] = 0.f; a2[i][j] = 0.f; }

    for (int k0 = 0; k0 < NINP; k0 += EBK) {
#pragma unroll
        for (int r = 0; r < 2; r++) {
            int idx = tid + r * 256;
            int m = idx >> 3, qq = idx & 7;
            float4 v = make_float4(0.f, 0.f, 0.f, 0.f);
            if (mBase + m < N_NODES)
                v = *(const float4*)(x + (size_t)(mBase + m) * NINP + k0 + qq * 4);
            *(float4*)&Xs[m][qq * 4] = v;
        }
#pragma unroll
        for (int r = 0; r < 2; r++) {
            int idx = tid + r * 256;
            int kr = idx >> 4, nq = idx & 15;
            *(float4*)&B1s[kr][nq * 4] = *(const float4*)(W11 + (size_t)(k0 + kr) * 64 + nq * 4);
            *(float4*)&B2s[kr][nq * 4] = *(const float4*)(W12 + (size_t)(k0 + kr) * 64 + nq * 4);
        }
        __syncthreads();
#pragma unroll
        for (int k = 0; k < EBK; k++) {
            float av[4];
#pragma unroll
            for (int i = 0; i < 4; i++) av[i] = Xs[ty * 4 + i][k];
            float4 b1 = *(float4*)&B1s[k][tx * 4];
            float4 b2 = *(float4*)&B2s[k][tx * 4];
#pragma unroll
            for (int i = 0; i < 4; i++) {
                a1[i][0] = fmaf(av[i], b1.x, a1[i][0]);
                a1[i][1] = fmaf(av[i], b1.y, a1[i][1]);
                a1[i][2] = fmaf(av[i], b1.z, a1[i][2]);
                a1[i][3] = fmaf(av[i], b1.w, a1[i][3]);
                a2[i][0] = fmaf(av[i], b2.x, a2[i][0]);
                a2[i][1] = fmaf(av[i], b2.y, a2[i][1]);
                a2[i][2] = fmaf(av[i], b2.z, a2[i][2]);
                a2[i][3] = fmaf(av[i], b2.w, a2[i][3]);
            }
        }
        __syncthreads();
    }
    float4 c1 = *(const float4*)(b11 + tx * 4);
    float4 c2 = *(const float4*)(b12 + tx * 4);
#pragma unroll
    for (int i = 0; i < 4; i++) {
        int m = mBase + ty * 4 + i;
        if (m < N_NODES) {
            float4 v;
            v.x = tanh_prod(a1[i][0] + c1.x, a2[i][0] + c2.x);
            v.y = tanh_prod(a1[i][1] + c1.y, a2[i][1] + c2.y);
            v.z = tanh_prod(a1[i][2] + c1.z, a2[i][2] + c2.z);
            v.w = tanh_prod(a1[i][3] + c1.w, a2[i][3] + c2.w);
            *(float4*)(out + (size_t)m * OUTC + NOUT1 + tx * 4) = v;
        }
    }
}

// ---------------- launch: fork/join stream DAG with agg->spectral pipeline ----
extern "C" void kernel_launch(void* const* d_in, const int* in_sizes, int n_in,
                              void* d_out, int out_size) {
    const float* x   = (const float*)d_in[0];
    const void*  ei  = d_in[1];
    const float* ea  = (const float*)d_in[2];
    const float* W1  = (const float*)d_in[3];
    const float* W2  = (const float*)d_in[4];
    const float* W3  = (const float*)d_in[5];
    const float* W4  = (const float*)d_in[6];
    const float* Wk  = (const float*)d_in[7];
    const float* bk  = (const float*)d_in[8];
    const float* W11 = (const float*)d_in[9];
    const float* b11 = (const float*)d_in[10];
    const float* W12 = (const float*)d_in[11];
    const float* b12 = (const float*)d_in[12];
    float* out = (float*)d_out;

    static cudaStream_t s1 = nullptr, s2 = nullptr;
    static cudaEvent_t evF, ev1, ev2, evA0, evS;
    if (!s1) {
        cudaStreamCreateWithFlags(&s1, cudaStreamNonBlocking);
        cudaStreamCreateWithFlags(&s2, cudaStreamNonBlocking);
        cudaEventCreateWithFlags(&evF,  cudaEventDisableTiming);
        cudaEventCreateWithFlags(&ev1,  cudaEventDisableTiming);
        cudaEventCreateWithFlags(&ev2,  cudaEventDisableTiming);
        cudaEventCreateWithFlags(&evA0, cudaEventDisableTiming);
        cudaEventCreateWithFlags(&evS,  cudaEventDisableTiming);
        cudaFuncSetAttribute(edge_mma_kernel,
                             cudaFuncAttributeMaxDynamicSharedMemorySize, EW_SMEM);
        cudaFuncSetAttribute(spectral_mma_kernel,
                             cudaFuncAttributeMaxDynamicSharedMemorySize, SP_SMEM);
    }

    // fork
    cudaEventRecord(evF, 0);
    cudaStreamWaitEvent(s1, evF, 0);
    cudaStreamWaitEvent(s2, evF, 0);

    // branch s2: edge MLP (independent of CSR build)
    edge_mma_kernel<<<1250, 256, EW_SMEM, s2>>>(ea, W1, W2, W3, W4);
    cudaEventRecord(ev2, s2);

    // branch s1: elementwise output + Wk conversion
    elem_kernel<<<(N_NODES + EBM - 1) / EBM, 256, 0, s1>>>(x, W11, b11, W12, b12, out);
    wk_convert_kernel<<<512, 256, 0, s1>>>(Wk);
    cudaEventRecord(ev1, s1);

    // main branch (default stream): CSR build
    detect_zero_kernel<<<(N_NODES + 255) / 256, 256>>>((const unsigned int*)ei);
    hist_kernel<<<N_EDGES / 256, 256>>>(ei);
    scan_partial_kernel<<<(N_NODES + 1023) / 1024, 1024>>>();
    scan_apply_kernel<<<(N_NODES + 1023) / 1024, 1024>>>();
    scatter_kernel<<<N_EDGES / 256, 256>>>(ei);

    // join: aggregation chunk 0 needs CSR + edge feats
    cudaStreamWaitEvent(0, ev2, 0);
    aggregate_kernel<<<(2 * NHALF + 7) / 8, 256>>>(x, 0, NHALF);
    cudaEventRecord(evA0, 0);

    // pipeline: spectral chunk 0 on s1 (needs wk [in-order on s1] + agg chunk 0)
    cudaStreamWaitEvent(s1, evA0, 0);
    spectral_mma_kernel<<<NHALF / 128, 256, SP_SMEM, s1>>>(bk, out, 0);
    cudaEventRecord(evS, s1);

    // default: aggregation chunk 1 runs concurrently with spectral chunk 0
    aggregate_kernel<<<(2 * (N_NODES - NHALF) + 7) / 8, 256>>>(x, NHALF, N_NODES);

    // spectral chunk 1 (needs wk + agg chunk 1)
    cudaStreamWaitEvent(0, ev1, 0);
    spectral_mma_kernel<<<(N_NODES - NHALF + 127) / 128, 256, SP_SMEM>>>(bk, out, NHALF);

    // rejoin s1 before capture end
    cudaStreamWaitEvent(0, evS, 0);
}

// round 14
// speedup vs baseline: 1.0401x; 1.0401x over previous
#include <cuda_runtime.h>
#include <cuda_bf16.h>
#include <math.h>

#define N_NODES 50000
#define N_EDGES 800000
#define NINP 128
#define NE 32
#define KSUP 8
#define NOUT1 128
#define NOUT2 64
#define OUTC 192

// ---------------- device scratch ---------------------------------------------
__device__ float g_e[(size_t)N_EDGES * KSUP];             // edge feats, EDGE order
__device__ int   g_deg[N_NODES];
__device__ int   g_off[N_NODES + 1];
__device__ int   g_cur[N_NODES];
__device__ int   g_eid[N_EDGES];                          // CSR slot -> edge id
__device__ int   g_src[N_EDGES];                          // CSR slot -> src node
__device__ int   g_part[64];
__device__ __nv_bfloat16 g_Hh[(size_t)(N_NODES + 128) * KSUP * NINP]; // H hi
__device__ __nv_bfloat16 g_Hl[(size_t)(N_NODES + 128) * KSUP * NINP]; // H lo
__device__ __nv_bfloat16 g_Wkh[KSUP * NINP * NOUT1];      // TRANSPOSED [n][k]
__device__ __nv_bfloat16 g_Wkl[KSUP * NINP * NOUT1];      // TRANSPOSED [n][k]
__device__ int   g_is64;

// ---------------- zero-MUFU exp2 / tanh-product ------------------------------
__device__ __forceinline__ float exp2k(float a) {   // ~= e^{2a}
    float y = fminf(fmaxf(a * 2.885390081777927f, -28.f), 28.f);
    float n = rintf(y);
    float f = y - n;
    float p = 1.3333558e-3f;
    p = fmaf(p, f, 9.6181291e-3f);
    p = fmaf(p, f, 5.5504109e-2f);
    p = fmaf(p, f, 2.4022651e-1f);
    p = fmaf(p, f, 6.9314718e-1f);
    p = fmaf(p, f, 1.0f);
    return __int_as_float(__float_as_int(p) + (((int)n) << 23));
}
__device__ __forceinline__ float tanh_prod(float a, float b) { // tanh(a)*tanh(b)
    float za = exp2k(a), zb = exp2k(b);
    float num = (za - 1.f) * (zb - 1.f);
    float den = (za + 1.f) * (zb + 1.f);
    float r = __int_as_float(0x7EF311C3 - __float_as_int(den));
    r = r * fmaf(-den, r, 2.f);
    r = r * fmaf(-den, r, 2.f);
    return num * r;
}

__device__ __forceinline__ int load_idx(const void* ei, long long pos, int is64) {
    if (is64) return (int)((const long long*)ei)[pos];
    return ((const int*)ei)[pos];
}

// ---------------- cp.async helpers -------------------------------------------
__device__ __forceinline__ void cp16(void* dst_smem, const void* src) {
    unsigned d = (unsigned)__cvta_generic_to_shared(dst_smem);
    asm volatile("cp.async.cg.shared.global [%0], [%1], 16;" :: "r"(d), "l"(src));
}
#define CP_COMMIT() asm volatile("cp.async.commit_group;" ::: "memory")
#define CP_WAIT1()  asm volatile("cp.async.wait_group 1;" ::: "memory")
#define CP_WAIT0()  asm volatile("cp.async.wait_group 0;" ::: "memory")

// ---------------- detect idx dtype + zero deg --------------------------------
__global__ void detect_zero_kernel(const unsigned int* __restrict__ ei) {
    int i = blockIdx.x * blockDim.x + threadIdx.x;
    if (i < N_NODES) g_deg[i] = 0;
    if (blockIdx.x == 0 && threadIdx.x == 0) {
        int is64 = 1;
        for (int k = 0; k < 128; k++)
            if (ei[2 * k + 1] != 0u) { is64 = 0; break; }
        g_is64 = is64;
    }
}

// ---------------- CSR build --------------------------------------------------
__global__ void hist_kernel(const void* __restrict__ ei) {
    int e = blockIdx.x * blockDim.x + threadIdx.x;
    if (e >= N_EDGES) return;
    int dst = load_idx(ei, (long long)N_EDGES + e, g_is64);
    atomicAdd(&g_deg[dst], 1);
}

__global__ void scan_partial_kernel() {
    __shared__ int s[1024];
    int i = blockIdx.x * 1024 + threadIdx.x;
    s[threadIdx.x] = (i < N_NODES) ? g_deg[i] : 0;
    __syncthreads();
    for (int d = 512; d > 0; d >>= 1) {
        if (threadIdx.x < d) s[threadIdx.x] += s[threadIdx.x + d];
        __syncthreads();
    }
    if (threadIdx.x == 0) g_part[blockIdx.x] = s[0];
}

__global__ void scan_apply_kernel() {
    __shared__ int sp[64];
    __shared__ int s[1024];
    int tid = threadIdx.x;
    int nblk = gridDim.x;
    if (tid == 0) {
        int run = 0;
        for (int i = 0; i < nblk; i++) { int t = g_part[i]; sp[i] = run; run += t; }
    }
    __syncthreads();
    int base = sp[blockIdx.x];
    int i = blockIdx.x * 1024 + tid;
    int v = (i < N_NODES) ? g_deg[i] : 0;
    s[tid] = v;
    __syncthreads();
    for (int d = 1; d < 1024; d <<= 1) {
        int t = (tid >= d) ? s[tid - d] : 0;
        __syncthreads();
        s[tid] += t;
        __syncthreads();
    }
    int incl = base + s[tid];
    if (i < N_NODES) { g_off[i + 1] = incl; g_cur[i] = incl - v; }
    if (blockIdx.x == 0 && tid == 0) g_off[0] = 0;
}

__global__ void scatter_kernel(const void* __restrict__ ei) {
    int e = blockIdx.x * blockDim.x + threadIdx.x;
    if (e >= N_EDGES) return;
    int is64 = g_is64;
    int dst = load_idx(ei, (long long)N_EDGES + e, is64);
    int src = load_idx(ei, e, is64);
    int p = atomicAdd(&g_cur[dst], 1);
    g_eid[p] = e;
    g_src[p] = src;
}

// ---------------- bf16-split mma helper --------------------------------------
__device__ __forceinline__ void mma_bf16(float* d, unsigned a0, unsigned a1,
                                         unsigned a2, unsigned a3,
                                         unsigned b0, unsigned b1) {
    asm volatile(
        "mma.sync.aligned.m16n8k16.row.col.f32.bf16.bf16.f32 "
        "{%0,%1,%2,%3},{%4,%5,%6,%7},{%8,%9},{%0,%1,%2,%3};"
        : "+f"(d[0]), "+f"(d[1]), "+f"(d[2]), "+f"(d[3])
        : "r"(a0), "r"(a1), "r"(a2), "r"(a3), "r"(b0), "r"(b1));
}

__device__ __forceinline__ void pack_hl(float x, float y, unsigned& hi, unsigned& lo) {
    __nv_bfloat16 hx = __float2bfloat16(x), hy = __float2bfloat16(y);
    __nv_bfloat162 hp; hp.x = hx; hp.y = hy;
    hi = *(unsigned*)&hp;
    __nv_bfloat162 lp;
    lp.x = __float2bfloat16(x - __bfloat162float(hx));
    lp.y = __float2bfloat16(y - __bfloat162float(hy));
    lo = *(unsigned*)&lp;
}

// ---------------- Wk hi/lo precompute (TRANSPOSED) ---------------------------
__global__ void wk_convert_kernel(const float* __restrict__ Wk) {
    int i = blockIdx.x * 256 + threadIdx.x;   // 131072 total
    int k = i >> 7, n = i & 127;
    float v = Wk[i];
    __nv_bfloat16 h = __float2bfloat16(v);
    g_Wkh[(size_t)n * 1024 + k] = h;
    g_Wkl[(size_t)n * 1024 + k] = __float2bfloat16(v - __bfloat162float(h));
}

// ---------------- edge MLP via tensor cores (A-fragments from global) --------
// Smem holds only weights; chunk loop is fully sync-free.
#define EW_SMEM 35072
#define ECHUNKS 5
__global__ void __launch_bounds__(256, 3) edge_mma_kernel(
        const float* __restrict__ ea, const float* __restrict__ W1,
        const float* __restrict__ W2, const float* __restrict__ W3,
        const float* __restrict__ W4) {
    extern __shared__ char sbuf[];
    __nv_bfloat16* Bh  = (__nv_bfloat16*)sbuf;             // [192][40]
    __nv_bfloat16* Bl  = (__nv_bfloat16*)(sbuf + 15360);
    __nv_bfloat16* W4h = (__nv_bfloat16*)(sbuf + 30720);   // [8 cols][136 k]
    __nv_bfloat16* W4l = (__nv_bfloat16*)(sbuf + 32896);

    int tid = threadIdx.x;
    int lane = tid & 31, w = tid >> 5;
    int g = lane >> 2, c2 = (lane & 3) * 2;

    // stage weights ONCE
    for (int idx = tid; idx < 6144; idx += 256) {
        int n = idx >> 5, k = idx & 31;
        int s = n >> 6, j = n & 63;
        const float* Wp = (s == 0) ? W1 : (s == 1) ? W2 : W3;
        float v = Wp[k * 64 + j];
        __nv_bfloat16 h = __float2bfloat16(v);
        Bh[n * 40 + k] = h;
        Bl[n * 40 + k] = __float2bfloat16(v - __bfloat162float(h));
    }
    for (int idx = tid; idx < 1024; idx += 256) {
        int kk = idx >> 3, c = idx & 7;
        float v = W4[idx];
        __nv_bfloat16 h = __float2bfloat16(v);
        W4h[c * 136 + kk] = h;
        W4l[c * 136 + kk] = __float2bfloat16(v - __bfloat162float(h));
    }
    __syncthreads();   // the only barrier in the kernel

    int m0 = w * 16 + g;
    for (int ch = 0; ch < ECHUNKS; ch++) {
        long long eBase = ((long long)blockIdx.x * ECHUNKS + ch) * 128;
        const float* ar = ea + (eBase + m0) * NE;   // row m0+g of this chunk

        // A fragments straight from global (L1-cached, fully consumed rows)
        unsigned ah[2][4], al[2][4];
#pragma unroll
        for (int kc = 0; kc < 2; kc++) {
            int kb = kc * 16 + c2;
            float2 v00 = *(const float2*)(ar + kb);            // row g,   k
            float2 v10 = *(const float2*)(ar + 8 * NE + kb);   // row g+8, k
            float2 v01 = *(const float2*)(ar + kb + 8);        // row g,   k+8
            float2 v11 = *(const float2*)(ar + 8 * NE + kb + 8);
            pack_hl(v00.x, v00.y, ah[kc][0], al[kc][0]);
            pack_hl(v10.x, v10.y, ah[kc][1], al[kc][1]);
            pack_hl(v01.x, v01.y, ah[kc][2], al[kc][2]);
            pack_hl(v11.x, v11.y, ah[kc][3], al[kc][3]);
        }

        float o[4] = {0.f, 0.f, 0.f, 0.f};
#pragma unroll
        for (int jp = 0; jp < 4; jp++) {
            int ko = jp * 16;
            unsigned linH[4], linL[4], mulH[4], mulL[4];
#pragma unroll
            for (int sub = 0; sub < 2; sub++) {
                int j = ko + sub * 8;
                float lin[4] = {0.f, 0.f, 0.f, 0.f};
                float t2[4]  = {0.f, 0.f, 0.f, 0.f};
                float t3[4]  = {0.f, 0.f, 0.f, 0.f};
#pragma unroll
                for (int kc = 0; kc < 2; kc++) {
                    int kb = kc * 16 + c2;
                    {
                        int n = j + g;
                        unsigned bh0 = *(unsigned*)&Bh[n * 40 + kb];
                        unsigned bh1 = *(unsigned*)&Bh[n * 40 + kb + 8];
                        unsigned bl0 = *(unsigned*)&Bl[n * 40 + kb];
                        unsigned bl1 = *(unsigned*)&Bl[n * 40 + kb + 8];
                        mma_bf16(lin, ah[kc][0], ah[kc][1], ah[kc][2], ah[kc][3], bh0, bh1);
                        mma_bf16(lin, ah[kc][0], ah[kc][1], ah[kc][2], ah[kc][3], bl0, bl1);
                        mma_bf16(lin, al[kc][0], al[kc][1], al[kc][2], al[kc][3], bh0, bh1);
                    }
                    {
                        int n = 64 + j + g;
                        unsigned bh0 = *(unsigned*)&Bh[n * 40 + kb];
                        unsigned bh1 = *(unsigned*)&Bh[n * 40 + kb + 8];
                        unsigned bl0 = *(unsigned*)&Bl[n * 40 + kb];
                        unsigned bl1 = *(unsigned*)&Bl[n * 40 + kb + 8];
                        mma_bf16(t2, ah[kc][0], ah[kc][1], ah[kc][2], ah[kc][3], bh0, bh1);
                        mma_bf16(t2, ah[kc][0], ah[kc][1], ah[kc][2], ah[kc][3], bl0, bl1);
                        mma_bf16(t2, al[kc][0], al[kc][1], al[kc][2], al[kc][3], bh0, bh1);
                    }
                    {
                        int n = 128 + j + g;
                        unsigned bh0 = *(unsigned*)&Bh[n * 40 + kb];
                        unsigned bh1 = *(unsigned*)&Bh[n * 40 + kb + 8];
                        unsigned bl0 = *(unsigned*)&Bl[n * 40 + kb];
                        unsigned bl1 = *(unsigned*)&Bl[n * 40 + kb + 8];
                        mma_bf16(t3, ah[kc][0], ah[kc][1], ah[kc][2], ah[kc][3], bh0, bh1);
                        mma_bf16(t3, ah[kc][0], ah[kc][1], ah[kc][2], ah[kc][3], bl0, bl1);
                        mma_bf16(t3, al[kc][0], al[kc][1], al[kc][2], al[kc][3], bh0, bh1);
                    }
                }
                float lv0 = fmaxf(lin[0], 0.f), lv1 = fmaxf(lin[1], 0.f);
                float lv2 = fmaxf(lin[2], 0.f), lv3 = fmaxf(lin[3], 0.f);
                float mv0 = tanh_prod(t2[0], t3[0]), mv1 = tanh_prod(t2[1], t3[1]);
                float mv2 = tanh_prod(t2[2], t3[2]), mv3 = tanh_prod(t2[3], t3[3]);
                pack_hl(lv0, lv1, linH[sub * 2],     linL[sub * 2]);
                pack_hl(lv2, lv3, linH[sub * 2 + 1], linL[sub * 2 + 1]);
                pack_hl(mv0, mv1, mulH[sub * 2],     mulL[sub * 2]);
                pack_hl(mv2, mv3, mulH[sub * 2 + 1], mulL[sub * 2 + 1]);
            }
            {
                int kb = ko + c2;
                unsigned b0h = *(unsigned*)&W4h[g * 136 + kb];
                unsigned b1h = *(unsigned*)&W4h[g * 136 + kb + 8];
                unsigned b0l = *(unsigned*)&W4l[g * 136 + kb];
                unsigned b1l = *(unsigned*)&W4l[g * 136 + kb + 8];
                mma_bf16(o, linH[0], linH[1], linH[2], linH[3], b0h, b1h);
                mma_bf16(o, linH[0], linH[1], linH[2], linH[3], b0l, b1l);
                mma_bf16(o, linL[0], linL[1], linL[2], linL[3], b0h, b1h);
            }
            {
                int kb = 64 + ko + c2;
                unsigned b0h = *(unsigned*)&W4h[g * 136 + kb];
                unsigned b1h = *(unsigned*)&W4h[g * 136 + kb + 8];
                unsigned b0l = *(unsigned*)&W4l[g * 136 + kb];
                unsigned b1l = *(unsigned*)&W4l[g * 136 + kb + 8];
                mma_bf16(o, mulH[0], mulH[1], mulH[2], mulH[3], b0h, b1h);
                mma_bf16(o, mulH[0], mulH[1], mulH[2], mulH[3], b0l, b1l);
                mma_bf16(o, mulL[0], mulL[1], mulL[2], mulL[3], b0h, b1h);
            }
        }
        long long e0 = eBase + m0;
        *(float2*)&g_e[e0 * 8 + c2] =
            make_float2(fmaxf(o[0], 0.f), fmaxf(o[1], 0.f));
        *(float2*)&g_e[(e0 + 8) * 8 + c2] =
            make_float2(fmaxf(o[2], 0.f), fmaxf(o[3], 0.f));
    }
}

// ---------------- per-node aggregation (2 warps per node, unroll x2) ---------
__global__ void aggregate_kernel(const float* __restrict__ x) {
    int gw = (blockIdx.x * blockDim.x + threadIdx.x) >> 5;
    int node = gw >> 1;
    if (node >= N_NODES) return;
    int half = gw & 1;
    int lane = threadIdx.x & 31;
    int cbase = half * 64 + lane * 2;

    float acc[8][2];
#pragma unroll
    for (int k = 0; k < 8; k++) { acc[k][0] = 0.f; acc[k][1] = 0.f; }

    int s = g_off[node], t = g_off[node + 1];
    int p = s;
    for (; p + 1 < t; p += 2) {
        int e0i = g_eid[p], e1i = g_eid[p + 1];
        int src0 = g_src[p], src1 = g_src[p + 1];
        float2 xv0 = *(const float2*)(x + (size_t)src0 * NINP + cbase);
        float2 xv1 = *(const float2*)(x + (size_t)src1 * NINP + cbase);
        const float4* ep0 = (const float4*)(g_e + (size_t)e0i * 8);
        const float4* ep1 = (const float4*)(g_e + (size_t)e1i * 8);
        float4 a0 = ep0[0], a1 = ep0[1], b0 = ep1[0], b1 = ep1[1];
        float ek0[8] = {a0.x, a0.y, a0.z, a0.w, a1.x, a1.y, a1.z, a1.w};
        float ek1[8] = {b0.x, b0.y, b0.z, b0.w, b1.x, b1.y, b1.z, b1.w};
#pragma unroll
        for (int k = 0; k < 8; k++) {
            acc[k][0] = fmaf(ek0[k], xv0.x, acc[k][0]);
            acc[k][1] = fmaf(ek0[k], xv0.y, acc[k][1]);
            acc[k][0] = fmaf(ek1[k], xv1.x, acc[k][0]);
            acc[k][1] = fmaf(ek1[k], xv1.y, acc[k][1]);
        }
    }
    if (p < t) {
        int e0i = g_eid[p];
        int src0 = g_src[p];
        float2 xv0 = *(const float2*)(x + (size_t)src0 * NINP + cbase);
        const float4* ep0 = (const float4*)(g_e + (size_t)e0i * 8);
        float4 a0 = ep0[0], a1 = ep0[1];
        float ek0[8] = {a0.x, a0.y, a0.z, a0.w, a1.x, a1.y, a1.z, a1.w};
#pragma unroll
        for (int k = 0; k < 8; k++) {
            acc[k][0] = fmaf(ek0[k], xv0.x, acc[k][0]);
            acc[k][1] = fmaf(ek0[k], xv0.y, acc[k][1]);
        }
    }
    size_t base = (size_t)node * (KSUP * NINP) + cbase;
#pragma unroll
    for (int k = 0; k < 8; k++) {
        unsigned hi, lo;
        pack_hl(acc[k][0], acc[k][1], hi, lo);
        *(unsigned*)&g_Hh[base + k * NINP] = hi;
        *(unsigned*)&g_Hl[base + k * NINP] = lo;
    }
}

// ---------------- spectral GEMM: cp.async double-buffered bf16 mma -----------
#define SP_SMEM 81920
__global__ void __launch_bounds__(256) spectral_mma_kernel(
        const float* __restrict__ bk, float* __restrict__ out) {
    extern __shared__ __nv_bfloat16 sm[];
    __nv_bfloat16* Ah = sm;               // 2 x 10240 B
    __nv_bfloat16* Al = sm + 10240;
    __nv_bfloat16* Bh = sm + 20480;
    __nv_bfloat16* Bl = sm + 30720;

    int tid  = threadIdx.x;
    int lane = tid & 31;
    int w    = tid >> 5;
    int wm   = (w & 3) * 32;
    int wn   = (w >> 2) * 64;
    int g    = lane >> 2;
    int c2   = (lane & 3) * 2;
    int mBase = blockIdx.x * 128;

    float acc[2][8][4];
#pragma unroll
    for (int mt = 0; mt < 2; mt++)
#pragma unroll
        for (int nt = 0; nt < 8; nt++)
#pragma unroll
            for (int qq = 0; qq < 4; qq++) acc[mt][nt][qq] = 0.f;

    auto stage = [&](int s, int kc) {
        int o = s * 5120;
#pragma unroll
        for (int i = 0; i < 2; i++) {
            int idx = tid + i * 256;
            int row = idx >> 2, q = (idx & 3) * 8;
            size_t ga = (size_t)(mBase + row) * 1024 + kc + q;
            cp16(&Ah[o + row * 40 + q], g_Hh + ga);
            cp16(&Al[o + row * 40 + q], g_Hl + ga);
            size_t wa = (size_t)row * 1024 + kc + q;
            cp16(&Bh[o + row * 40 + q], g_Wkh + wa);
            cp16(&Bl[o + row * 40 + q], g_Wkl + wa);
        }
    };

    stage(0, 0);
    CP_COMMIT();

    for (int c = 0; c < 32; c++) {
        int cur = c & 1;
        if (c + 1 < 32) {
            stage((c + 1) & 1, (c + 1) * 32);
            CP_COMMIT();
            CP_WAIT1();
        } else {
            CP_WAIT0();
        }
        __syncthreads();

        int ob = cur * 5120;
#pragma unroll
        for (int ks = 0; ks < 2; ks++) {
            int ko = ks * 16;
            unsigned ah[2][4], al[2][4];
#pragma unroll
            for (int mt = 0; mt < 2; mt++) {
                int r0 = (wm + mt * 16 + g) * 40 + ob + ko + c2;
                ah[mt][0] = *(const unsigned*)&Ah[r0];
                ah[mt][1] = *(const unsigned*)&Ah[r0 + 8 * 40];
                ah[mt][2] = *(const unsigned*)&Ah[r0 + 8];
                ah[mt][3] = *(const unsigned*)&Ah[r0 + 8 * 40 + 8];
                al[mt][0] = *(const unsigned*)&Al[r0];
                al[mt][1] = *(const unsigned*)&Al[r0 + 8 * 40];
                al[mt][2] = *(const unsigned*)&Al[r0 + 8];
                al[mt][3] = *(const unsigned*)&Al[r0 + 8 * 40 + 8];
            }
#pragma unroll
            for (int nt = 0; nt < 8; nt++) {
                int n0 = (wn + nt * 8 + g) * 40 + ob + ko + c2;
                unsigned bh0 = *(const unsigned*)&Bh[n0];
                unsigned bh1 = *(const unsigned*)&Bh[n0 + 8];
                unsigned bl0 = *(const unsigned*)&Bl[n0];
                unsigned bl1 = *(const unsigned*)&Bl[n0 + 8];
#pragma unroll
                for (int mt = 0; mt < 2; mt++) {
                    mma_bf16(acc[mt][nt], ah[mt][0], ah[mt][1], ah[mt][2], ah[mt][3], bh0, bh1);
                    mma_bf16(acc[mt][nt], ah[mt][0], ah[mt][1], ah[mt][2], ah[mt][3], bl0, bl1);
                    mma_bf16(acc[mt][nt], al[mt][0], al[mt][1], al[mt][2], al[mt][3], bh0, bh1);
                }
            }
        }
        __syncthreads();
    }

#pragma unroll
    for (int mt = 0; mt < 2; mt++) {
        int row0 = mBase + wm + mt * 16 + g;
        int row1 = row0 + 8;
#pragma unroll
        for (int nt = 0; nt < 8; nt++) {
            int col = wn + nt * 8 + c2;
            float bx = bk[col], by = bk[col + 1];
            if (row0 < N_NODES) {
                float2 v = make_float2(fmaxf(acc[mt][nt][0] + bx, 0.f),
                                       fmaxf(acc[mt][nt][1] + by, 0.f));
                *(float2*)(out + (size_t)row0 * OUTC + col) = v;
            }
            if (row1 < N_NODES) {
                float2 v = make_float2(fmaxf(acc[mt][nt][2] + bx, 0.f),
                                       fmaxf(acc[mt][nt][3] + by, 0.f));
                *(float2*)(out + (size_t)row1 * OUTC + col) = v;
            }
        }
    }
}

// ---------------- elementwise branch -----------------------------------------
#define EBM 64
#define EBK 32
__global__ void elem_kernel(const float* __restrict__ x,
                            const float* __restrict__ W11,
                            const float* __restrict__ b11,
                            const float* __restrict__ W12,
                            const float* __restrict__ b12,
                            float* __restrict__ out) {
    __shared__ float Xs[EBM][36];
    __shared__ float B1s[EBK][64];
    __shared__ float B2s[EBK][64];
    int tid = threadIdx.x;
    int tx = tid & 15;
    int ty = tid >> 4;
    int mBase = blockIdx.x * EBM;

    float a1[4][4], a2[4][4];
#pragma unroll
    for (int i = 0; i < 4; i++)
#pragma unroll
        for (int j = 0; j < 4; j++) { a1[i][j] = 0.f; a2[i][j] = 0.f; }

    for (int k0 = 0; k0 < NINP; k0 += EBK) {
#pragma unroll
        for (int r = 0; r < 2; r++) {
            int idx = tid + r * 256;
            int m = idx >> 3, qq = idx & 7;
            float4 v = make_float4(0.f, 0.f, 0.f, 0.f);
            if (mBase + m < N_NODES)
                v = *(const float4*)(x + (size_t)(mBase + m) * NINP + k0 + qq * 4);
            *(float4*)&Xs[m][qq * 4] = v;
        }
#pragma unroll
        for (int r = 0; r < 2; r++) {
            int idx = tid + r * 256;
            int kr = idx >> 4, nq = idx & 15;
            *(float4*)&B1s[kr][nq * 4] = *(const float4*)(W11 + (size_t)(k0 + kr) * 64 + nq * 4);
            *(float4*)&B2s[kr][nq * 4] = *(const float4*)(W12 + (size_t)(k0 + kr) * 64 + nq * 4);
        }
        __syncthreads();
#pragma unroll
        for (int k = 0; k < EBK; k++) {
            float av[4];
#pragma unroll
            for (int i = 0; i < 4; i++) av[i] = Xs[ty * 4 + i][k];
            float4 b1 = *(float4*)&B1s[k][tx * 4];
            float4 b2 = *(float4*)&B2s[k][tx * 4];
#pragma unroll
            for (int i = 0; i < 4; i++) {
                a1[i][0] = fmaf(av[i], b1.x, a1[i][0]);
                a1[i][1] = fmaf(av[i], b1.y, a1[i][1]);
                a1[i][2] = fmaf(av[i], b1.z, a1[i][2]);
                a1[i][3] = fmaf(av[i], b1.w, a1[i][3]);
                a2[i][0] = fmaf(av[i], b2.x, a2[i][0]);
                a2[i][1] = fmaf(av[i], b2.y, a2[i][1]);
                a2[i][2] = fmaf(av[i], b2.z, a2[i][2]);
                a2[i][3] = fmaf(av[i], b2.w, a2[i][3]);
            }
        }
        __syncthreads();
    }
    float4 c1 = *(const float4*)(b11 + tx * 4);
    float4 c2 = *(const float4*)(b12 + tx * 4);
#pragma unroll
    for (int i = 0; i < 4; i++) {
        int m = mBase + ty * 4 + i;
        if (m < N_NODES) {
            float4 v;
            v.x = tanh_prod(a1[i][0] + c1.x, a2[i][0] + c2.x);
            v.y = tanh_prod(a1[i][1] + c1.y, a2[i][1] + c2.y);
            v.z = tanh_prod(a1[i][2] + c1.z, a2[i][2] + c2.z);
            v.w = tanh_prod(a1[i][3] + c1.w, a2[i][3] + c2.w);
            *(float4*)(out + (size_t)m * OUTC + NOUT1 + tx * 4) = v;
        }
    }
}

// ---------------- launch: fork/join stream DAG (R12 form) ---------------------
extern "C" void kernel_launch(void* const* d_in, const int* in_sizes, int n_in,
                              void* d_out, int out_size) {
    const float* x   = (const float*)d_in[0];
    const void*  ei  = d_in[1];
    const float* ea  = (const float*)d_in[2];
    const float* W1  = (const float*)d_in[3];
    const float* W2  = (const float*)d_in[4];
    const float* W3  = (const float*)d_in[5];
    const float* W4  = (const float*)d_in[6];
    const float* Wk  = (const float*)d_in[7];
    const float* bk  = (const float*)d_in[8];
    const float* W11 = (const float*)d_in[9];
    const float* b11 = (const float*)d_in[10];
    const float* W12 = (const float*)d_in[11];
    const float* b12 = (const float*)d_in[12];
    float* out = (float*)d_out;

    static cudaStream_t s1 = nullptr, s2 = nullptr;
    static cudaEvent_t evF, ev1, ev2;
    if (!s1) {
        cudaStreamCreateWithFlags(&s1, cudaStreamNonBlocking);
        cudaStreamCreateWithFlags(&s2, cudaStreamNonBlocking);
        cudaEventCreateWithFlags(&evF, cudaEventDisableTiming);
        cudaEventCreateWithFlags(&ev1, cudaEventDisableTiming);
        cudaEventCreateWithFlags(&ev2, cudaEventDisableTiming);
        cudaFuncSetAttribute(edge_mma_kernel,
                             cudaFuncAttributeMaxDynamicSharedMemorySize, EW_SMEM);
        cudaFuncSetAttribute(spectral_mma_kernel,
                             cudaFuncAttributeMaxDynamicSharedMemorySize, SP_SMEM);
    }

    // fork
    cudaEventRecord(evF, 0);
    cudaStreamWaitEvent(s1, evF, 0);
    cudaStreamWaitEvent(s2, evF, 0);

    // branch s2: edge MLP (independent of CSR build)
    edge_mma_kernel<<<1250, 256, EW_SMEM, s2>>>(ea, W1, W2, W3, W4);
    cudaEventRecord(ev2, s2);

    // branch s1: elementwise output + Wk conversion
    elem_kernel<<<(N_NODES + EBM - 1) / EBM, 256, 0, s1>>>(x, W11, b11, W12, b12, out);
    wk_convert_kernel<<<512, 256, 0, s1>>>(Wk);
    cudaEventRecord(ev1, s1);

    // main branch (default stream): CSR build
    detect_zero_kernel<<<(N_NODES + 255) / 256, 256>>>((const unsigned int*)ei);
    hist_kernel<<<N_EDGES / 256, 256>>>(ei);
    scan_partial_kernel<<<(N_NODES + 1023) / 1024, 1024>>>();
    scan_apply_kernel<<<(N_NODES + 1023) / 1024, 1024>>>();
    scatter_kernel<<<N_EDGES / 256, 256>>>(ei);

    // join: aggregate needs CSR (default) + edge feats (s2)
    cudaStreamWaitEvent(0, ev2, 0);
    aggregate_kernel<<<(2 * N_NODES + 7) / 8, 256>>>(x);

    // join: spectral needs aggregate (default) + Wk conversion (s1)
    cudaStreamWaitEvent(0, ev1, 0);
    spectral_mma_kernel<<<(N_NODES + 127) / 128, 256, SP_SMEM>>>(bk, out);
}

// round 15
// speedup vs baseline: 1.0448x; 1.0046x over previous
#include <cuda_runtime.h>
#include <cuda_bf16.h>
#include <math.h>

#define N_NODES 50000
#define N_EDGES 800000
#define NINP 128
#define NE 32
#define KSUP 8
#define NOUT1 128
#define NOUT2 64
#define OUTC 192

// ---------------- device scratch ---------------------------------------------
__device__ float g_e[(size_t)N_EDGES * KSUP];             // edge feats, EDGE order
__device__ int   g_deg[N_NODES];
__device__ int   g_off[N_NODES + 1];
__device__ int   g_cur[N_NODES];
__device__ int2  g_se[N_EDGES];                           // CSR slot -> (src, eid)
__device__ int   g_part[64];
__device__ __nv_bfloat16 g_Hh[(size_t)(N_NODES + 128) * KSUP * NINP]; // H hi
__device__ __nv_bfloat16 g_Hl[(size_t)(N_NODES + 128) * KSUP * NINP]; // H lo
__device__ __nv_bfloat16 g_Wkh[KSUP * NINP * NOUT1];      // TRANSPOSED [n][k]
__device__ __nv_bfloat16 g_Wkl[KSUP * NINP * NOUT1];      // TRANSPOSED [n][k]
__device__ int   g_is64;

// ---------------- zero-MUFU exp2 / tanh-product ------------------------------
__device__ __forceinline__ float exp2k(float a) {   // ~= e^{2a}
    float y = fminf(fmaxf(a * 2.885390081777927f, -28.f), 28.f);
    float n = rintf(y);
    float f = y - n;
    float p = 1.3333558e-3f;
    p = fmaf(p, f, 9.6181291e-3f);
    p = fmaf(p, f, 5.5504109e-2f);
    p = fmaf(p, f, 2.4022651e-1f);
    p = fmaf(p, f, 6.9314718e-1f);
    p = fmaf(p, f, 1.0f);
    return __int_as_float(__float_as_int(p) + (((int)n) << 23));
}
__device__ __forceinline__ float tanh_prod(float a, float b) { // tanh(a)*tanh(b)
    float za = exp2k(a), zb = exp2k(b);
    float num = (za - 1.f) * (zb - 1.f);
    float den = (za + 1.f) * (zb + 1.f);
    float r = __int_as_float(0x7EF311C3 - __float_as_int(den));
    r = r * fmaf(-den, r, 2.f);
    r = r * fmaf(-den, r, 2.f);
    return num * r;
}

__device__ __forceinline__ int load_idx(const void* ei, long long pos, int is64) {
    if (is64) return (int)((const long long*)ei)[pos];
    return ((const int*)ei)[pos];
}

// ---------------- cp.async helpers -------------------------------------------
__device__ __forceinline__ void cp16(void* dst_smem, const void* src) {
    unsigned d = (unsigned)__cvta_generic_to_shared(dst_smem);
    asm volatile("cp.async.cg.shared.global [%0], [%1], 16;" :: "r"(d), "l"(src));
}
#define CP_COMMIT() asm volatile("cp.async.commit_group;" ::: "memory")
#define CP_WAIT1()  asm volatile("cp.async.wait_group 1;" ::: "memory")
#define CP_WAIT0()  asm volatile("cp.async.wait_group 0;" ::: "memory")

// ---------------- detect idx dtype + zero deg --------------------------------
__global__ void detect_zero_kernel(const unsigned int* __restrict__ ei) {
    int i = blockIdx.x * blockDim.x + threadIdx.x;
    if (i < N_NODES) g_deg[i] = 0;
    if (blockIdx.x == 0 && threadIdx.x == 0) {
        int is64 = 1;
        for (int k = 0; k < 128; k++)
            if (ei[2 * k + 1] != 0u) { is64 = 0; break; }
        g_is64 = is64;
    }
}

// ---------------- CSR build --------------------------------------------------
__global__ void hist_kernel(const void* __restrict__ ei) {
    int e = blockIdx.x * blockDim.x + threadIdx.x;
    if (e >= N_EDGES) return;
    int dst = load_idx(ei, (long long)N_EDGES + e, g_is64);
    atomicAdd(&g_deg[dst], 1);
}

__global__ void scan_partial_kernel() {
    __shared__ int s[1024];
    int i = blockIdx.x * 1024 + threadIdx.x;
    s[threadIdx.x] = (i < N_NODES) ? g_deg[i] : 0;
    __syncthreads();
    for (int d = 512; d > 0; d >>= 1) {
        if (threadIdx.x < d) s[threadIdx.x] += s[threadIdx.x + d];
        __syncthreads();
    }
    if (threadIdx.x == 0) g_part[blockIdx.x] = s[0];
}

__global__ void scan_apply_kernel() {
    __shared__ int sp[64];
    __shared__ int s[1024];
    int tid = threadIdx.x;
    int nblk = gridDim.x;
    if (tid == 0) {
        int run = 0;
        for (int i = 0; i < nblk; i++) { int t = g_part[i]; sp[i] = run; run += t; }
    }
    __syncthreads();
    int base = sp[blockIdx.x];
    int i = blockIdx.x * 1024 + tid;
    int v = (i < N_NODES) ? g_deg[i] : 0;
    s[tid] = v;
    __syncthreads();
    for (int d = 1; d < 1024; d <<= 1) {
        int t = (tid >= d) ? s[tid - d] : 0;
        __syncthreads();
        s[tid] += t;
        __syncthreads();
    }
    int incl = base + s[tid];
    if (i < N_NODES) { g_off[i + 1] = incl; g_cur[i] = incl - v; }
    if (blockIdx.x == 0 && tid == 0) g_off[0] = 0;
}

__global__ void scatter_kernel(const void* __restrict__ ei) {
    int e = blockIdx.x * blockDim.x + threadIdx.x;
    if (e >= N_EDGES) return;
    int is64 = g_is64;
    int dst = load_idx(ei, (long long)N_EDGES + e, is64);
    int src = load_idx(ei, e, is64);
    int p = atomicAdd(&g_cur[dst], 1);
    g_se[p] = make_int2(src, e);
}

// ---------------- bf16-split mma helper --------------------------------------
__device__ __forceinline__ void mma_bf16(float* d, unsigned a0, unsigned a1,
                                         unsigned a2, unsigned a3,
                                         unsigned b0, unsigned b1) {
    asm volatile(
        "mma.sync.aligned.m16n8k16.row.col.f32.bf16.bf16.f32 "
        "{%0,%1,%2,%3},{%4,%5,%6,%7},{%8,%9},{%0,%1,%2,%3};"
        : "+f"(d[0]), "+f"(d[1]), "+f"(d[2]), "+f"(d[3])
        : "r"(a0), "r"(a1), "r"(a2), "r"(a3), "r"(b0), "r"(b1));
}

__device__ __forceinline__ void pack_hl(float x, float y, unsigned& hi, unsigned& lo) {
    __nv_bfloat16 hx = __float2bfloat16(x), hy = __float2bfloat16(y);
    __nv_bfloat162 hp; hp.x = hx; hp.y = hy;
    hi = *(unsigned*)&hp;
    __nv_bfloat162 lp;
    lp.x = __float2bfloat16(x - __bfloat162float(hx));
    lp.y = __float2bfloat16(y - __bfloat162float(hy));
    lo = *(unsigned*)&lp;
}

// ---------------- Wk hi/lo precompute (TRANSPOSED) ---------------------------
__global__ void wk_convert_kernel(const float* __restrict__ Wk) {
    int i = blockIdx.x * 256 + threadIdx.x;   // 131072 total
    int k = i >> 7, n = i & 127;
    float v = Wk[i];
    __nv_bfloat16 h = __float2bfloat16(v);
    g_Wkh[(size_t)n * 1024 + k] = h;
    g_Wkl[(size_t)n * 1024 + k] = __float2bfloat16(v - __bfloat162float(h));
}

// ---------------- edge MLP via tensor cores (A-fragments from global) --------
#define EW_SMEM 35072
#define ECHUNKS 5
__global__ void __launch_bounds__(256, 3) edge_mma_kernel(
        const float* __restrict__ ea, const float* __restrict__ W1,
        const float* __restrict__ W2, const float* __restrict__ W3,
        const float* __restrict__ W4) {
    extern __shared__ char sbuf[];
    __nv_bfloat16* Bh  = (__nv_bfloat16*)sbuf;             // [192][40]
    __nv_bfloat16* Bl  = (__nv_bfloat16*)(sbuf + 15360);
    __nv_bfloat16* W4h = (__nv_bfloat16*)(sbuf + 30720);   // [8 cols][136 k]
    __nv_bfloat16* W4l = (__nv_bfloat16*)(sbuf + 32896);

    int tid = threadIdx.x;
    int lane = tid & 31, w = tid >> 5;
    int g = lane >> 2, c2 = (lane & 3) * 2;

    for (int idx = tid; idx < 6144; idx += 256) {
        int n = idx >> 5, k = idx & 31;
        int s = n >> 6, j = n & 63;
        const float* Wp = (s == 0) ? W1 : (s == 1) ? W2 : W3;
        float v = Wp[k * 64 + j];
        __nv_bfloat16 h = __float2bfloat16(v);
        Bh[n * 40 + k] = h;
        Bl[n * 40 + k] = __float2bfloat16(v - __bfloat162float(h));
    }
    for (int idx = tid; idx < 1024; idx += 256) {
        int kk = idx >> 3, c = idx & 7;
        float v = W4[idx];
        __nv_bfloat16 h = __float2bfloat16(v);
        W4h[c * 136 + kk] = h;
        W4l[c * 136 + kk] = __float2bfloat16(v - __bfloat162float(h));
    }
    __syncthreads();   // the only barrier in the kernel

    int m0 = w * 16 + g;
    for (int ch = 0; ch < ECHUNKS; ch++) {
        long long eBase = ((long long)blockIdx.x * ECHUNKS + ch) * 128;
        const float* ar = ea + (eBase + m0) * NE;

        unsigned ah[2][4], al[2][4];
#pragma unroll
        for (int kc = 0; kc < 2; kc++) {
            int kb = kc * 16 + c2;
            float2 v00 = *(const float2*)(ar + kb);
            float2 v10 = *(const float2*)(ar + 8 * NE + kb);
            float2 v01 = *(const float2*)(ar + kb + 8);
            float2 v11 = *(const float2*)(ar + 8 * NE + kb + 8);
            pack_hl(v00.x, v00.y, ah[kc][0], al[kc][0]);
            pack_hl(v10.x, v10.y, ah[kc][1], al[kc][1]);
            pack_hl(v01.x, v01.y, ah[kc][2], al[kc][2]);
            pack_hl(v11.x, v11.y, ah[kc][3], al[kc][3]);
        }

        float o[4] = {0.f, 0.f, 0.f, 0.f};
#pragma unroll
        for (int jp = 0; jp < 4; jp++) {
            int ko = jp * 16;
            unsigned linH[4], linL[4], mulH[4], mulL[4];
#pragma unroll
            for (int sub = 0; sub < 2; sub++) {
                int j = ko + sub * 8;
                float lin[4] = {0.f, 0.f, 0.f, 0.f};
                float t2[4]  = {0.f, 0.f, 0.f, 0.f};
                float t3[4]  = {0.f, 0.f, 0.f, 0.f};
#pragma unroll
                for (int kc = 0; kc < 2; kc++) {
                    int kb = kc * 16 + c2;
                    {
                        int n = j + g;
                        unsigned bh0 = *(unsigned*)&Bh[n * 40 + kb];
                        unsigned bh1 = *(unsigned*)&Bh[n * 40 + kb + 8];
                        unsigned bl0 = *(unsigned*)&Bl[n * 40 + kb];
                        unsigned bl1 = *(unsigned*)&Bl[n * 40 + kb + 8];
                        mma_bf16(lin, ah[kc][0], ah[kc][1], ah[kc][2], ah[kc][3], bh0, bh1);
                        mma_bf16(lin, ah[kc][0], ah[kc][1], ah[kc][2], ah[kc][3], bl0, bl1);
                        mma_bf16(lin, al[kc][0], al[kc][1], al[kc][2], al[kc][3], bh0, bh1);
                    }
                    {
                        int n = 64 + j + g;
                        unsigned bh0 = *(unsigned*)&Bh[n * 40 + kb];
                        unsigned bh1 = *(unsigned*)&Bh[n * 40 + kb + 8];
                        unsigned bl0 = *(unsigned*)&Bl[n * 40 + kb];
                        unsigned bl1 = *(unsigned*)&Bl[n * 40 + kb + 8];
                        mma_bf16(t2, ah[kc][0], ah[kc][1], ah[kc][2], ah[kc][3], bh0, bh1);
                        mma_bf16(t2, ah[kc][0], ah[kc][1], ah[kc][2], ah[kc][3], bl0, bl1);
                        mma_bf16(t2, al[kc][0], al[kc][1], al[kc][2], al[kc][3], bh0, bh1);
                    }
                    {
                        int n = 128 + j + g;
                        unsigned bh0 = *(unsigned*)&Bh[n * 40 + kb];
                        unsigned bh1 = *(unsigned*)&Bh[n * 40 + kb + 8];
                        unsigned bl0 = *(unsigned*)&Bl[n * 40 + kb];
                        unsigned bl1 = *(unsigned*)&Bl[n * 40 + kb + 8];
                        mma_bf16(t3, ah[kc][0], ah[kc][1], ah[kc][2], ah[kc][3], bh0, bh1);
                        mma_bf16(t3, ah[kc][0], ah[kc][1], ah[kc][2], ah[kc][3], bl0, bl1);
                        mma_bf16(t3, al[kc][0], al[kc][1], al[kc][2], al[kc][3], bh0, bh1);
                    }
                }
                float lv0 = fmaxf(lin[0], 0.f), lv1 = fmaxf(lin[1], 0.f);
                float lv2 = fmaxf(lin[2], 0.f), lv3 = fmaxf(lin[3], 0.f);
                float mv0 = tanh_prod(t2[0], t3[0]), mv1 = tanh_prod(t2[1], t3[1]);
                float mv2 = tanh_prod(t2[2], t3[2]), mv3 = tanh_prod(t2[3], t3[3]);
                pack_hl(lv0, lv1, linH[sub * 2],     linL[sub * 2]);
                pack_hl(lv2, lv3, linH[sub * 2 + 1], linL[sub * 2 + 1]);
                pack_hl(mv0, mv1, mulH[sub * 2],     mulL[sub * 2]);
                pack_hl(mv2, mv3, mulH[sub * 2 + 1], mulL[sub * 2 + 1]);
            }
            {
                int kb = ko + c2;
                unsigned b0h = *(unsigned*)&W4h[g * 136 + kb];
                unsigned b1h = *(unsigned*)&W4h[g * 136 + kb + 8];
                unsigned b0l = *(unsigned*)&W4l[g * 136 + kb];
                unsigned b1l = *(unsigned*)&W4l[g * 136 + kb + 8];
                mma_bf16(o, linH[0], linH[1], linH[2], linH[3], b0h, b1h);
                mma_bf16(o, linH[0], linH[1], linH[2], linH[3], b0l, b1l);
                mma_bf16(o, linL[0], linL[1], linL[2], linL[3], b0h, b1h);
            }
            {
                int kb = 64 + ko + c2;
                unsigned b0h = *(unsigned*)&W4h[g * 136 + kb];
                unsigned b1h = *(unsigned*)&W4h[g * 136 + kb + 8];
                unsigned b0l = *(unsigned*)&W4l[g * 136 + kb];
                unsigned b1l = *(unsigned*)&W4l[g * 136 + kb + 8];
                mma_bf16(o, mulH[0], mulH[1], mulH[2], mulH[3], b0h, b1h);
                mma_bf16(o, mulH[0], mulH[1], mulH[2], mulH[3], b0l, b1l);
                mma_bf16(o, mulL[0], mulL[1], mulL[2], mulL[3], b0h, b1h);
            }
        }
        long long e0 = eBase + m0;
        *(float2*)&g_e[e0 * 8 + c2] =
            make_float2(fmaxf(o[0], 0.f), fmaxf(o[1], 0.f));
        *(float2*)&g_e[(e0 + 8) * 8 + c2] =
            make_float2(fmaxf(o[2], 0.f), fmaxf(o[3], 0.f));
    }
}

// ---------------- per-node aggregation (warp per node, float4, unroll x2) ----
__global__ void aggregate_kernel(const float* __restrict__ x) {
    int gw = (blockIdx.x * blockDim.x + threadIdx.x) >> 5;
    if (gw >= N_NODES) return;
    int lane = threadIdx.x & 31;
    int c4 = lane * 4;

    float acc[8][4];
#pragma unroll
    for (int k = 0; k < 8; k++)
#pragma unroll
        for (int c = 0; c < 4; c++) acc[k][c] = 0.f;

    int s = g_off[gw], t = g_off[gw + 1];
    int p = s;
    for (; p + 1 < t; p += 2) {
        int2 se0 = g_se[p], se1 = g_se[p + 1];
        float4 xv0 = *(const float4*)(x + (size_t)se0.x * NINP + c4);
        float4 xv1 = *(const float4*)(x + (size_t)se1.x * NINP + c4);
        const float4* ep0 = (const float4*)(g_e + (size_t)se0.y * 8);
        const float4* ep1 = (const float4*)(g_e + (size_t)se1.y * 8);
        float4 a0 = ep0[0], a1 = ep0[1], b0 = ep1[0], b1 = ep1[1];
        float ek0[8] = {a0.x, a0.y, a0.z, a0.w, a1.x, a1.y, a1.z, a1.w};
        float ek1[8] = {b0.x, b0.y, b0.z, b0.w, b1.x, b1.y, b1.z, b1.w};
#pragma unroll
        for (int k = 0; k < 8; k++) {
            acc[k][0] = fmaf(ek0[k], xv0.x, acc[k][0]);
            acc[k][1] = fmaf(ek0[k], xv0.y, acc[k][1]);
            acc[k][2] = fmaf(ek0[k], xv0.z, acc[k][2]);
            acc[k][3] = fmaf(ek0[k], xv0.w, acc[k][3]);
            acc[k][0] = fmaf(ek1[k], xv1.x, acc[k][0]);
            acc[k][1] = fmaf(ek1[k], xv1.y, acc[k][1]);
            acc[k][2] = fmaf(ek1[k], xv1.z, acc[k][2]);
            acc[k][3] = fmaf(ek1[k], xv1.w, acc[k][3]);
        }
    }
    if (p < t) {
        int2 se0 = g_se[p];
        float4 xv0 = *(const float4*)(x + (size_t)se0.x * NINP + c4);
        const float4* ep0 = (const float4*)(g_e + (size_t)se0.y * 8);
        float4 a0 = ep0[0], a1 = ep0[1];
        float ek0[8] = {a0.x, a0.y, a0.z, a0.w, a1.x, a1.y, a1.z, a1.w};
#pragma unroll
        for (int k = 0; k < 8; k++) {
            acc[k][0] = fmaf(ek0[k], xv0.x, acc[k][0]);
            acc[k][1] = fmaf(ek0[k], xv0.y, acc[k][1]);
            acc[k][2] = fmaf(ek0[k], xv0.z, acc[k][2]);
            acc[k][3] = fmaf(ek0[k], xv0.w, acc[k][3]);
        }
    }
    size_t base = (size_t)gw * (KSUP * NINP) + c4;
#pragma unroll
    for (int k = 0; k < 8; k++) {
        unsigned h0, l0, h1, l1;
        pack_hl(acc[k][0], acc[k][1], h0, l0);
        pack_hl(acc[k][2], acc[k][3], h1, l1);
        *(uint2*)&g_Hh[base + k * NINP] = make_uint2(h0, h1);
        *(uint2*)&g_Hl[base + k * NINP] = make_uint2(l0, l1);
    }
}

// ---------------- spectral GEMM: cp.async double-buffered bf16 mma -----------
#define SP_SMEM 81920
__global__ void __launch_bounds__(256) spectral_mma_kernel(
        const float* __restrict__ bk, float* __restrict__ out) {
    extern __shared__ __nv_bfloat16 sm[];
    __nv_bfloat16* Ah = sm;               // 2 x 10240 B
    __nv_bfloat16* Al = sm + 10240;
    __nv_bfloat16* Bh = sm + 20480;
    __nv_bfloat16* Bl = sm + 30720;

    int tid  = threadIdx.x;
    int lane = tid & 31;
    int w    = tid >> 5;
    int wm   = (w & 3) * 32;
    int wn   = (w >> 2) * 64;
    int g    = lane >> 2;
    int c2   = (lane & 3) * 2;
    int mBase = blockIdx.x * 128;

    float acc[2][8][4];
#pragma unroll
    for (int mt = 0; mt < 2; mt++)
#pragma unroll
        for (int nt = 0; nt < 8; nt++)
#pragma unroll
            for (int qq = 0; qq < 4; qq++) acc[mt][nt][qq] = 0.f;

    auto stage = [&](int s, int kc) {
        int o = s * 5120;
#pragma unroll
        for (int i = 0; i < 2; i++) {
            int idx = tid + i * 256;
            int row = idx >> 2, q = (idx & 3) * 8;
            size_t ga = (size_t)(mBase + row) * 1024 + kc + q;
            cp16(&Ah[o + row * 40 + q], g_Hh + ga);
            cp16(&Al[o + row * 40 + q], g_Hl + ga);
            size_t wa = (size_t)row * 1024 + kc + q;
            cp16(&Bh[o + row * 40 + q], g_Wkh + wa);
            cp16(&Bl[o + row * 40 + q], g_Wkl + wa);
        }
    };

    stage(0, 0);
    CP_COMMIT();

    for (int c = 0; c < 32; c++) {
        int cur = c & 1;
        if (c + 1 < 32) {
            stage((c + 1) & 1, (c + 1) * 32);
            CP_COMMIT();
            CP_WAIT1();
        } else {
            CP_WAIT0();
        }
        __syncthreads();

        int ob = cur * 5120;
#pragma unroll
        for (int ks = 0; ks < 2; ks++) {
            int ko = ks * 16;
            unsigned ah[2][4], al[2][4];
#pragma unroll
            for (int mt = 0; mt < 2; mt++) {
                int r0 = (wm + mt * 16 + g) * 40 + ob + ko + c2;
                ah[mt][0] = *(const unsigned*)&Ah[r0];
                ah[mt][1] = *(const unsigned*)&Ah[r0 + 8 * 40];
                ah[mt][2] = *(const unsigned*)&Ah[r0 + 8];
                ah[mt][3] = *(const unsigned*)&Ah[r0 + 8 * 40 + 8];
                al[mt][0] = *(const unsigned*)&Al[r0];
                al[mt][1] = *(const unsigned*)&Al[r0 + 8 * 40];
                al[mt][2] = *(const unsigned*)&Al[r0 + 8];
                al[mt][3] = *(const unsigned*)&Al[r0 + 8 * 40 + 8];
            }
#pragma unroll
            for (int nt = 0; nt < 8; nt++) {
                int n0 = (wn + nt * 8 + g) * 40 + ob + ko + c2;
                unsigned bh0 = *(const unsigned*)&Bh[n0];
                unsigned bh1 = *(const unsigned*)&Bh[n0 + 8];
                unsigned bl0 = *(const unsigned*)&Bl[n0];
                unsigned bl1 = *(const unsigned*)&Bl[n0 + 8];
#pragma unroll
                for (int mt = 0; mt < 2; mt++) {
                    mma_bf16(acc[mt][nt], ah[mt][0], ah[mt][1], ah[mt][2], ah[mt][3], bh0, bh1);
                    mma_bf16(acc[mt][nt], ah[mt][0], ah[mt][1], ah[mt][2], ah[mt][3], bl0, bl1);
                    mma_bf16(acc[mt][nt], al[mt][0], al[mt][1], al[mt][2], al[mt][3], bh0, bh1);
                }
            }
        }
        __syncthreads();
    }

#pragma unroll
    for (int mt = 0; mt < 2; mt++) {
        int row0 = mBase + wm + mt * 16 + g;
        int row1 = row0 + 8;
#pragma unroll
        for (int nt = 0; nt < 8; nt++) {
            int col = wn + nt * 8 + c2;
            float bx = bk[col], by = bk[col + 1];
            if (row0 < N_NODES) {
                float2 v = make_float2(fmaxf(acc[mt][nt][0] + bx, 0.f),
                                       fmaxf(acc[mt][nt][1] + by, 0.f));
                *(float2*)(out + (size_t)row0 * OUTC + col) = v;
            }
            if (row1 < N_NODES) {
                float2 v = make_float2(fmaxf(acc[mt][nt][2] + bx, 0.f),
                                       fmaxf(acc[mt][nt][3] + by, 0.f));
                *(float2*)(out + (size_t)row1 * OUTC + col) = v;
            }
        }
    }
}

// ---------------- elementwise branch -----------------------------------------
#define EBM 64
#define EBK 32
__global__ void elem_kernel(const float* __restrict__ x,
                            const float* __restrict__ W11,
                            const float* __restrict__ b11,
                            const float* __restrict__ W12,
                            const float* __restrict__ b12,
                            float* __restrict__ out) {
    __shared__ float Xs[EBM][36];
    __shared__ float B1s[EBK][64];
    __shared__ float B2s[EBK][64];
    int tid = threadIdx.x;
    int tx = tid & 15;
    int ty = tid >> 4;
    int mBase = blockIdx.x * EBM;

    float a1[4][4], a2[4][4];
#pragma unroll
    for (int i = 0; i < 4; i++)
#pragma unroll
        for (int j = 0; j < 4; j++) { a1[i][j] = 0.f; a2[i][j] = 0.f; }

    for (int k0 = 0; k0 < NINP; k0 += EBK) {
#pragma unroll
        for (int r = 0; r < 2; r++) {
            int idx = tid + r * 256;
            int m = idx >> 3, qq = idx & 7;
            float4 v = make_float4(0.f, 0.f, 0.f, 0.f);
            if (mBase + m < N_NODES)
                v = *(const float4*)(x + (size_t)(mBase + m) * NINP + k0 + qq * 4);
            *(float4*)&Xs[m][qq * 4] = v;
        }
#pragma unroll
        for (int r = 0; r < 2; r++) {
            int idx = tid + r * 256;
            int kr = idx >> 4, nq = idx & 15;
            *(float4*)&B1s[kr][nq * 4] = *(const float4*)(W11 + (size_t)(k0 + kr) * 64 + nq * 4);
            *(float4*)&B2s[kr][nq * 4] = *(const float4*)(W12 + (size_t)(k0 + kr) * 64 + nq * 4);
        }
        __syncthreads();
#pragma unroll
        for (int k = 0; k < EBK; k++) {
            float av[4];
#pragma unroll
            for (int i = 0; i < 4; i++) av[i] = Xs[ty * 4 + i][k];
            float4 b1 = *(float4*)&B1s[k][tx * 4];
            float4 b2 = *(float4*)&B2s[k][tx * 4];
#pragma unroll
            for (int i = 0; i < 4; i++) {
                a1[i][0] = fmaf(av[i], b1.x, a1[i][0]);
                a1[i][1] = fmaf(av[i], b1.y, a1[i][1]);
                a1[i][2] = fmaf(av[i], b1.z, a1[i][2]);
                a1[i][3] = fmaf(av[i], b1.w, a1[i][3]);
                a2[i][0] = fmaf(av[i], b2.x, a2[i][0]);
                a2[i][1] = fmaf(av[i], b2.y, a2[i][1]);
                a2[i][2] = fmaf(av[i], b2.z, a2[i][2]);
                a2[i][3] = fmaf(av[i], b2.w, a2[i][3]);
            }
        }
        __syncthreads();
    }
    float4 c1 = *(const float4*)(b11 + tx * 4);
    float4 c2 = *(const float4*)(b12 + tx * 4);
#pragma unroll
    for (int i = 0; i < 4; i++) {
        int m = mBase + ty * 4 + i;
        if (m < N_NODES) {
            float4 v;
            v.x = tanh_prod(a1[i][0] + c1.x, a2[i][0] + c2.x);
            v.y = tanh_prod(a1[i][1] + c1.y, a2[i][1] + c2.y);
            v.z = tanh_prod(a1[i][2] + c1.z, a2[i][2] + c2.z);
            v.w = tanh_prod(a1[i][3] + c1.w, a2[i][3] + c2.w);
            *(float4*)(out + (size_t)m * OUTC + NOUT1 + tx * 4) = v;
        }
    }
}

// ---------------- launch: fork/join stream DAG (R12 form) ---------------------
extern "C" void kernel_launch(void* const* d_in, const int* in_sizes, int n_in,
                              void* d_out, int out_size) {
    const float* x   = (const float*)d_in[0];
    const void*  ei  = d_in[1];
    const float* ea  = (const float*)d_in[2];
    const float* W1  = (const float*)d_in[3];
    const float* W2  = (const float*)d_in[4];
    const float* W3  = (const float*)d_in[5];
    const float* W4  = (const float*)d_in[6];
    const float* Wk  = (const float*)d_in[7];
    const float* bk  = (const float*)d_in[8];
    const float* W11 = (const float*)d_in[9];
    const float* b11 = (const float*)d_in[10];
    const float* W12 = (const float*)d_in[11];
    const float* b12 = (const float*)d_in[12];
    float* out = (float*)d_out;

    static cudaStream_t s1 = nullptr, s2 = nullptr;
    static cudaEvent_t evF, ev1, ev2;
    if (!s1) {
        cudaStreamCreateWithFlags(&s1, cudaStreamNonBlocking);
        cudaStreamCreateWithFlags(&s2, cudaStreamNonBlocking);
        cudaEventCreateWithFlags(&evF, cudaEventDisableTiming);
        cudaEventCreateWithFlags(&ev1, cudaEventDisableTiming);
        cudaEventCreateWithFlags(&ev2, cudaEventDisableTiming);
        cudaFuncSetAttribute(edge_mma_kernel,
                             cudaFuncAttributeMaxDynamicSharedMemorySize, EW_SMEM);
        cudaFuncSetAttribute(spectral_mma_kernel,
                             cudaFuncAttributeMaxDynamicSharedMemorySize, SP_SMEM);
    }

    // fork
    cudaEventRecord(evF, 0);
    cudaStreamWaitEvent(s1, evF, 0);
    cudaStreamWaitEvent(s2, evF, 0);

    // branch s2: edge MLP (independent of CSR build)
    edge_mma_kernel<<<1250, 256, EW_SMEM, s2>>>(ea, W1, W2, W3, W4);
    cudaEventRecord(ev2, s2);

    // branch s1: elementwise output + Wk conversion
    elem_kernel<<<(N_NODES + EBM - 1) / EBM, 256, 0, s1>>>(x, W11, b11, W12, b12, out);
    wk_convert_kernel<<<512, 256, 0, s1>>>(Wk);
    cudaEventRecord(ev1, s1);

    // main branch (default stream): CSR build
    detect_zero_kernel<<<(N_NODES + 255) / 256, 256>>>((const unsigned int*)ei);
    hist_kernel<<<N_EDGES / 256, 256>>>(ei);
    scan_partial_kernel<<<(N_NODES + 1023) / 1024, 1024>>>();
    scan_apply_kernel<<<(N_NODES + 1023) / 1024, 1024>>>();
    scatter_kernel<<<N_EDGES / 256, 256>>>(ei);

    // join: aggregate needs CSR (default) + edge feats (s2)
    cudaStreamWaitEvent(0, ev2, 0);
    aggregate_kernel<<<(N_NODES + 7) / 8, 256>>>(x);

    // join: spectral needs aggregate (default) + Wk conversion (s1)
    cudaStreamWaitEvent(0, ev1, 0);
    spectral_mma_kernel<<<(N_NODES + 127) / 128, 256, SP_SMEM>>>(bk, out);
}

// round 16
// speedup vs baseline: 1.1396x; 1.0907x over previous
#include <cuda_runtime.h>
#include <cuda_bf16.h>
#include <cuda_fp16.h>
#include <math.h>

#define N_NODES 50000
#define N_EDGES 800000
#define NINP 128
#define NE 32
#define KSUP 8
#define NOUT1 128
#define NOUT2 64
#define OUTC 192

// ---------------- device scratch ---------------------------------------------
__device__ float g_e[(size_t)N_EDGES * KSUP];             // edge feats, EDGE order
__device__ int   g_deg[N_NODES];
__device__ int   g_off[N_NODES + 1];
__device__ int   g_cur[N_NODES];
__device__ int2  g_se[N_EDGES];                           // CSR slot -> (src, eid)
__device__ int   g_part[64];
__device__ __half g_Hf[(size_t)(N_NODES + 128) * KSUP * NINP];  // H fp16
__device__ __half g_Wkh[KSUP * NINP * NOUT1];             // TRANSPOSED [n][k], hi
__device__ __half g_Wkl[KSUP * NINP * NOUT1];             // TRANSPOSED [n][k], lo
__device__ int   g_is64;

// ---------------- zero-MUFU exp2 / tanh-product ------------------------------
__device__ __forceinline__ float exp2k(float a) {   // ~= e^{2a}
    float y = fminf(fmaxf(a * 2.885390081777927f, -28.f), 28.f);
    float n = rintf(y);
    float f = y - n;
    float p = 1.3333558e-3f;
    p = fmaf(p, f, 9.6181291e-3f);
    p = fmaf(p, f, 5.5504109e-2f);
    p = fmaf(p, f, 2.4022651e-1f);
    p = fmaf(p, f, 6.9314718e-1f);
    p = fmaf(p, f, 1.0f);
    return __int_as_float(__float_as_int(p) + (((int)n) << 23));
}
__device__ __forceinline__ float tanh_prod(float a, float b) { // tanh(a)*tanh(b)
    float za = exp2k(a), zb = exp2k(b);
    float num = (za - 1.f) * (zb - 1.f);
    float den = (za + 1.f) * (zb + 1.f);
    float r = __int_as_float(0x7EF311C3 - __float_as_int(den));
    r = r * fmaf(-den, r, 2.f);
    r = r * fmaf(-den, r, 2.f);
    return num * r;
}

__device__ __forceinline__ int load_idx(const void* ei, long long pos, int is64) {
    if (is64) return (int)((const long long*)ei)[pos];
    return ((const int*)ei)[pos];
}

// ---------------- cp.async helpers -------------------------------------------
__device__ __forceinline__ void cp16(void* dst_smem, const void* src) {
    unsigned d = (unsigned)__cvta_generic_to_shared(dst_smem);
    asm volatile("cp.async.cg.shared.global [%0], [%1], 16;" :: "r"(d), "l"(src));
}
#define CP_COMMIT() asm volatile("cp.async.commit_group;" ::: "memory")
#define CP_WAIT1()  asm volatile("cp.async.wait_group 1;" ::: "memory")
#define CP_WAIT0()  asm volatile("cp.async.wait_group 0;" ::: "memory")

// ---------------- detect idx dtype + zero deg --------------------------------
__global__ void detect_zero_kernel(const unsigned int* __restrict__ ei) {
    int i = blockIdx.x * blockDim.x + threadIdx.x;
    if (i < N_NODES) g_deg[i] = 0;
    if (blockIdx.x == 0 && threadIdx.x == 0) {
        int is64 = 1;
        for (int k = 0; k < 128; k++)
            if (ei[2 * k + 1] != 0u) { is64 = 0; break; }
        g_is64 = is64;
    }
}

// ---------------- CSR build --------------------------------------------------
__global__ void hist_kernel(const void* __restrict__ ei) {
    int e = blockIdx.x * blockDim.x + threadIdx.x;
    if (e >= N_EDGES) return;
    int dst = load_idx(ei, (long long)N_EDGES + e, g_is64);
    atomicAdd(&g_deg[dst], 1);
}

__global__ void scan_partial_kernel() {
    __shared__ int s[1024];
    int i = blockIdx.x * 1024 + threadIdx.x;
    s[threadIdx.x] = (i < N_NODES) ? g_deg[i] : 0;
    __syncthreads();
    for (int d = 512; d > 0; d >>= 1) {
        if (threadIdx.x < d) s[threadIdx.x] += s[threadIdx.x + d];
        __syncthreads();
    }
    if (threadIdx.x == 0) g_part[blockIdx.x] = s[0];
}

__global__ void scan_apply_kernel() {
    __shared__ int sp[64];
    __shared__ int s[1024];
    int tid = threadIdx.x;
    int nblk = gridDim.x;
    if (tid == 0) {
        int run = 0;
        for (int i = 0; i < nblk; i++) { int t = g_part[i]; sp[i] = run; run += t; }
    }
    __syncthreads();
    int base = sp[blockIdx.x];
    int i = blockIdx.x * 1024 + tid;
    int v = (i < N_NODES) ? g_deg[i] : 0;
    s[tid] = v;
    __syncthreads();
    for (int d = 1; d < 1024; d <<= 1) {
        int t = (tid >= d) ? s[tid - d] : 0;
        __syncthreads();
        s[tid] += t;
        __syncthreads();
    }
    int incl = base + s[tid];
    if (i < N_NODES) { g_off[i + 1] = incl; g_cur[i] = incl - v; }
    if (blockIdx.x == 0 && tid == 0) g_off[0] = 0;
}

__global__ void scatter_kernel(const void* __restrict__ ei) {
    int e = blockIdx.x * blockDim.x + threadIdx.x;
    if (e >= N_EDGES) return;
    int is64 = g_is64;
    int dst = load_idx(ei, (long long)N_EDGES + e, is64);
    int src = load_idx(ei, e, is64);
    int p = atomicAdd(&g_cur[dst], 1);
    g_se[p] = make_int2(src, e);
}

// ---------------- mma helpers -------------------------------------------------
__device__ __forceinline__ void mma_bf16(float* d, unsigned a0, unsigned a1,
                                         unsigned a2, unsigned a3,
                                         unsigned b0, unsigned b1) {
    asm volatile(
        "mma.sync.aligned.m16n8k16.row.col.f32.bf16.bf16.f32 "
        "{%0,%1,%2,%3},{%4,%5,%6,%7},{%8,%9},{%0,%1,%2,%3};"
        : "+f"(d[0]), "+f"(d[1]), "+f"(d[2]), "+f"(d[3])
        : "r"(a0), "r"(a1), "r"(a2), "r"(a3), "r"(b0), "r"(b1));
}
__device__ __forceinline__ void mma_f16(float* d, unsigned a0, unsigned a1,
                                        unsigned a2, unsigned a3,
                                        unsigned b0, unsigned b1) {
    asm volatile(
        "mma.sync.aligned.m16n8k16.row.col.f32.f16.f16.f32 "
        "{%0,%1,%2,%3},{%4,%5,%6,%7},{%8,%9},{%0,%1,%2,%3};"
        : "+f"(d[0]), "+f"(d[1]), "+f"(d[2]), "+f"(d[3])
        : "r"(a0), "r"(a1), "r"(a2), "r"(a3), "r"(b0), "r"(b1));
}

__device__ __forceinline__ void pack_hl(float x, float y, unsigned& hi, unsigned& lo) {
    __nv_bfloat16 hx = __float2bfloat16(x), hy = __float2bfloat16(y);
    __nv_bfloat162 hp; hp.x = hx; hp.y = hy;
    hi = *(unsigned*)&hp;
    __nv_bfloat162 lp;
    lp.x = __float2bfloat16(x - __bfloat162float(hx));
    lp.y = __float2bfloat16(y - __bfloat162float(hy));
    lo = *(unsigned*)&lp;
}
__device__ __forceinline__ unsigned pack_h2(float x, float y) {
    __half2 h = __floats2half2_rn(x, y);
    return *(unsigned*)&h;
}

// ---------------- Wk fp16 hi/lo precompute (TRANSPOSED) ----------------------
__global__ void wk_convert_kernel(const float* __restrict__ Wk) {
    int i = blockIdx.x * 256 + threadIdx.x;   // 131072 total
    int k = i >> 7, n = i & 127;
    float v = Wk[i];
    __half h = __float2half_rn(v);
    g_Wkh[(size_t)n * 1024 + k] = h;
    g_Wkl[(size_t)n * 1024 + k] = __float2half_rn(v - __half2float(h));
}

// ---------------- edge MLP via tensor cores (A-fragments from global) --------
#define EW_SMEM 35072
#define ECHUNKS 5
__global__ void __launch_bounds__(256, 3) edge_mma_kernel(
        const float* __restrict__ ea, const float* __restrict__ W1,
        const float* __restrict__ W2, const float* __restrict__ W3,
        const float* __restrict__ W4) {
    extern __shared__ char sbuf[];
    __nv_bfloat16* Bh  = (__nv_bfloat16*)sbuf;             // [192][40]
    __nv_bfloat16* Bl  = (__nv_bfloat16*)(sbuf + 15360);
    __nv_bfloat16* W4h = (__nv_bfloat16*)(sbuf + 30720);   // [8 cols][136 k]
    __nv_bfloat16* W4l = (__nv_bfloat16*)(sbuf + 32896);

    int tid = threadIdx.x;
    int lane = tid & 31, w = tid >> 5;
    int g = lane >> 2, c2 = (lane & 3) * 2;

    for (int idx = tid; idx < 6144; idx += 256) {
        int n = idx >> 5, k = idx & 31;
        int s = n >> 6, j = n & 63;
        const float* Wp = (s == 0) ? W1 : (s == 1) ? W2 : W3;
        float v = Wp[k * 64 + j];
        __nv_bfloat16 h = __float2bfloat16(v);
        Bh[n * 40 + k] = h;
        Bl[n * 40 + k] = __float2bfloat16(v - __bfloat162float(h));
    }
    for (int idx = tid; idx < 1024; idx += 256) {
        int kk = idx >> 3, c = idx & 7;
        float v = W4[idx];
        __nv_bfloat16 h = __float2bfloat16(v);
        W4h[c * 136 + kk] = h;
        W4l[c * 136 + kk] = __float2bfloat16(v - __bfloat162float(h));
    }
    __syncthreads();   // the only barrier in the kernel

    int m0 = w * 16 + g;
    for (int ch = 0; ch < ECHUNKS; ch++) {
        long long eBase = ((long long)blockIdx.x * ECHUNKS + ch) * 128;
        const float* ar = ea + (eBase + m0) * NE;

        unsigned ah[2][4], al[2][4];
#pragma unroll
        for (int kc = 0; kc < 2; kc++) {
            int kb = kc * 16 + c2;
            float2 v00 = *(const float2*)(ar + kb);
            float2 v10 = *(const float2*)(ar + 8 * NE + kb);
            float2 v01 = *(const float2*)(ar + kb + 8);
            float2 v11 = *(const float2*)(ar + 8 * NE + kb + 8);
            pack_hl(v00.x, v00.y, ah[kc][0], al[kc][0]);
            pack_hl(v10.x, v10.y, ah[kc][1], al[kc][1]);
            pack_hl(v01.x, v01.y, ah[kc][2], al[kc][2]);
            pack_hl(v11.x, v11.y, ah[kc][3], al[kc][3]);
        }

        float o[4] = {0.f, 0.f, 0.f, 0.f};
#pragma unroll
        for (int jp = 0; jp < 4; jp++) {
            int ko = jp * 16;
            unsigned linH[4], linL[4], mulH[4], mulL[4];
#pragma unroll
            for (int sub = 0; sub < 2; sub++) {
                int j = ko + sub * 8;
                float lin[4] = {0.f, 0.f, 0.f, 0.f};
                float t2[4]  = {0.f, 0.f, 0.f, 0.f};
                float t3[4]  = {0.f, 0.f, 0.f, 0.f};
#pragma unroll
                for (int kc = 0; kc < 2; kc++) {
                    int kb = kc * 16 + c2;
                    {
                        int n = j + g;
                        unsigned bh0 = *(unsigned*)&Bh[n * 40 + kb];
                        unsigned bh1 = *(unsigned*)&Bh[n * 40 + kb + 8];
                        unsigned bl0 = *(unsigned*)&Bl[n * 40 + kb];
                        unsigned bl1 = *(unsigned*)&Bl[n * 40 + kb + 8];
                        mma_bf16(lin, ah[kc][0], ah[kc][1], ah[kc][2], ah[kc][3], bh0, bh1);
                        mma_bf16(lin, ah[kc][0], ah[kc][1], ah[kc][2], ah[kc][3], bl0, bl1);
                        mma_bf16(lin, al[kc][0], al[kc][1], al[kc][2], al[kc][3], bh0, bh1);
                    }
                    {
                        int n = 64 + j + g;
                        unsigned bh0 = *(unsigned*)&Bh[n * 40 + kb];
                        unsigned bh1 = *(unsigned*)&Bh[n * 40 + kb + 8];
                        unsigned bl0 = *(unsigned*)&Bl[n * 40 + kb];
                        unsigned bl1 = *(unsigned*)&Bl[n * 40 + kb + 8];
                        mma_bf16(t2, ah[kc][0], ah[kc][1], ah[kc][2], ah[kc][3], bh0, bh1);
                        mma_bf16(t2, ah[kc][0], ah[kc][1], ah[kc][2], ah[kc][3], bl0, bl1);
                        mma_bf16(t2, al[kc][0], al[kc][1], al[kc][2], al[kc][3], bh0, bh1);
                    }
                    {
                        int n = 128 + j + g;
                        unsigned bh0 = *(unsigned*)&Bh[n * 40 + kb];
                        unsigned bh1 = *(unsigned*)&Bh[n * 40 + kb + 8];
                        unsigned bl0 = *(unsigned*)&Bl[n * 40 + kb];
                        unsigned bl1 = *(unsigned*)&Bl[n * 40 + kb + 8];
                        mma_bf16(t3, ah[kc][0], ah[kc][1], ah[kc][2], ah[kc][3], bh0, bh1);
                        mma_bf16(t3, ah[kc][0], ah[kc][1], ah[kc][2], ah[kc][3], bl0, bl1);
                        mma_bf16(t3, al[kc][0], al[kc][1], al[kc][2], al[kc][3], bh0, bh1);
                    }
                }
                float lv0 = fmaxf(lin[0], 0.f), lv1 = fmaxf(lin[1], 0.f);
                float lv2 = fmaxf(lin[2], 0.f), lv3 = fmaxf(lin[3], 0.f);
                float mv0 = tanh_prod(t2[0], t3[0]), mv1 = tanh_prod(t2[1], t3[1]);
                float mv2 = tanh_prod(t2[2], t3[2]), mv3 = tanh_prod(t2[3], t3[3]);
                pack_hl(lv0, lv1, linH[sub * 2],     linL[sub * 2]);
                pack_hl(lv2, lv3, linH[sub * 2 + 1], linL[sub * 2 + 1]);
                pack_hl(mv0, mv1, mulH[sub * 2],     mulL[sub * 2]);
                pack_hl(mv2, mv3, mulH[sub * 2 + 1], mulL[sub * 2 + 1]);
            }
            {
                int kb = ko + c2;
                unsigned b0h = *(unsigned*)&W4h[g * 136 + kb];
                unsigned b1h = *(unsigned*)&W4h[g * 136 + kb + 8];
                unsigned b0l = *(unsigned*)&W4l[g * 136 + kb];
                unsigned b1l = *(unsigned*)&W4l[g * 136 + kb + 8];
                mma_bf16(o, linH[0], linH[1], linH[2], linH[3], b0h, b1h);
                mma_bf16(o, linH[0], linH[1], linH[2], linH[3], b0l, b1l);
                mma_bf16(o, linL[0], linL[1], linL[2], linL[3], b0h, b1h);
            }
            {
                int kb = 64 + ko + c2;
                unsigned b0h = *(unsigned*)&W4h[g * 136 + kb];
                unsigned b1h = *(unsigned*)&W4h[g * 136 + kb + 8];
                unsigned b0l = *(unsigned*)&W4l[g * 136 + kb];
                unsigned b1l = *(unsigned*)&W4l[g * 136 + kb + 8];
                mma_bf16(o, mulH[0], mulH[1], mulH[2], mulH[3], b0h, b1h);
                mma_bf16(o, mulH[0], mulH[1], mulH[2], mulH[3], b0l, b1l);
                mma_bf16(o, mulL[0], mulL[1], mulL[2], mulL[3], b0h, b1h);
            }
        }
        long long e0 = eBase + m0;
        *(float2*)&g_e[e0 * 8 + c2] =
            make_float2(fmaxf(o[0], 0.f), fmaxf(o[1], 0.f));
        *(float2*)&g_e[(e0 + 8) * 8 + c2] =
            make_float2(fmaxf(o[2], 0.f), fmaxf(o[3], 0.f));
    }
}

// ---------------- per-node aggregation (warp per node, fp16 H out) -----------
__global__ void aggregate_kernel(const float* __restrict__ x) {
    int gw = (blockIdx.x * blockDim.x + threadIdx.x) >> 5;
    if (gw >= N_NODES) return;
    int lane = threadIdx.x & 31;
    int c4 = lane * 4;

    float acc[8][4];
#pragma unroll
    for (int k = 0; k < 8; k++)
#pragma unroll
        for (int c = 0; c < 4; c++) acc[k][c] = 0.f;

    int s = g_off[gw], t = g_off[gw + 1];
    int p = s;
    for (; p + 1 < t; p += 2) {
        int2 se0 = g_se[p], se1 = g_se[p + 1];
        float4 xv0 = *(const float4*)(x + (size_t)se0.x * NINP + c4);
        float4 xv1 = *(const float4*)(x + (size_t)se1.x * NINP + c4);
        const float4* ep0 = (const float4*)(g_e + (size_t)se0.y * 8);
        const float4* ep1 = (const float4*)(g_e + (size_t)se1.y * 8);
        float4 a0 = ep0[0], a1 = ep0[1], b0 = ep1[0], b1 = ep1[1];
        float ek0[8] = {a0.x, a0.y, a0.z, a0.w, a1.x, a1.y, a1.z, a1.w};
        float ek1[8] = {b0.x, b0.y, b0.z, b0.w, b1.x, b1.y, b1.z, b1.w};
#pragma unroll
        for (int k = 0; k < 8; k++) {
            acc[k][0] = fmaf(ek0[k], xv0.x, acc[k][0]);
            acc[k][1] = fmaf(ek0[k], xv0.y, acc[k][1]);
            acc[k][2] = fmaf(ek0[k], xv0.z, acc[k][2]);
            acc[k][3] = fmaf(ek0[k], xv0.w, acc[k][3]);
            acc[k][0] = fmaf(ek1[k], xv1.x, acc[k][0]);
            acc[k][1] = fmaf(ek1[k], xv1.y, acc[k][1]);
            acc[k][2] = fmaf(ek1[k], xv1.z, acc[k][2]);
            acc[k][3] = fmaf(ek1[k], xv1.w, acc[k][3]);
        }
    }
    if (p < t) {
        int2 se0 = g_se[p];
        float4 xv0 = *(const float4*)(x + (size_t)se0.x * NINP + c4);
        const float4* ep0 = (const float4*)(g_e + (size_t)se0.y * 8);
        float4 a0 = ep0[0], a1 = ep0[1];
        float ek0[8] = {a0.x, a0.y, a0.z, a0.w, a1.x, a1.y, a1.z, a1.w};
#pragma unroll
        for (int k = 0; k < 8; k++) {
            acc[k][0] = fmaf(ek0[k], xv0.x, acc[k][0]);
            acc[k][1] = fmaf(ek0[k], xv0.y, acc[k][1]);
            acc[k][2] = fmaf(ek0[k], xv0.z, acc[k][2]);
            acc[k][3] = fmaf(ek0[k], xv0.w, acc[k][3]);
        }
    }
    size_t base = (size_t)gw * (KSUP * NINP) + c4;
#pragma unroll
    for (int k = 0; k < 8; k++) {
        unsigned h0 = pack_h2(acc[k][0], acc[k][1]);
        unsigned h1 = pack_h2(acc[k][2], acc[k][3]);
        *(uint2*)&g_Hf[base + k * NINP] = make_uint2(h0, h1);
    }
}

// ---------------- spectral GEMM: fp16 A single, fp16 B hi/lo, 2x mma ---------
// Stage layout (halfwords): [2 stages][128 rows][40], stage stride 5120 hw.
#define SP_SMEM 61440
__global__ void __launch_bounds__(256) spectral_mma_kernel(
        const float* __restrict__ bk, float* __restrict__ out) {
    extern __shared__ __half smh[];
    __half* Ah = smh;                 // 2 x 10240 B
    __half* Bh = smh + 10240;
    __half* Bl = smh + 20480;

    int tid  = threadIdx.x;
    int lane = tid & 31;
    int w    = tid >> 5;
    int wm   = (w & 3) * 32;
    int wn   = (w >> 2) * 64;
    int g    = lane >> 2;
    int c2   = (lane & 3) * 2;
    int mBase = blockIdx.x * 128;

    float acc[2][8][4];
#pragma unroll
    for (int mt = 0; mt < 2; mt++)
#pragma unroll
        for (int nt = 0; nt < 8; nt++)
#pragma unroll
            for (int qq = 0; qq < 4; qq++) acc[mt][nt][qq] = 0.f;

    auto stage = [&](int s, int kc) {
        int o = s * 5120;
#pragma unroll
        for (int i = 0; i < 2; i++) {
            int idx = tid + i * 256;
            int row = idx >> 2, q = (idx & 3) * 8;
            size_t ga = (size_t)(mBase + row) * 1024 + kc + q;
            cp16(&Ah[o + row * 40 + q], g_Hf + ga);
            size_t wa = (size_t)row * 1024 + kc + q;   // row = n (transposed Wk)
            cp16(&Bh[o + row * 40 + q], g_Wkh + wa);
            cp16(&Bl[o + row * 40 + q], g_Wkl + wa);
        }
    };

    stage(0, 0);
    CP_COMMIT();

    for (int c = 0; c < 32; c++) {
        int cur = c & 1;
        if (c + 1 < 32) {
            stage((c + 1) & 1, (c + 1) * 32);
            CP_COMMIT();
            CP_WAIT1();
        } else {
            CP_WAIT0();
        }
        __syncthreads();

        int ob = cur * 5120;
#pragma unroll
        for (int ks = 0; ks < 2; ks++) {
            int ko = ks * 16;
            unsigned ah[2][4];
#pragma unroll
            for (int mt = 0; mt < 2; mt++) {
                int r0 = (wm + mt * 16 + g) * 40 + ob + ko + c2;
                ah[mt][0] = *(const unsigned*)&Ah[r0];
                ah[mt][1] = *(const unsigned*)&Ah[r0 + 8 * 40];
                ah[mt][2] = *(const unsigned*)&Ah[r0 + 8];
                ah[mt][3] = *(const unsigned*)&Ah[r0 + 8 * 40 + 8];
            }
#pragma unroll
            for (int nt = 0; nt < 8; nt++) {
                int n0 = (wn + nt * 8 + g) * 40 + ob + ko + c2;
                unsigned bh0 = *(const unsigned*)&Bh[n0];
                unsigned bh1 = *(const unsigned*)&Bh[n0 + 8];
                unsigned bl0 = *(const unsigned*)&Bl[n0];
                unsigned bl1 = *(const unsigned*)&Bl[n0 + 8];
#pragma unroll
                for (int mt = 0; mt < 2; mt++) {
                    mma_f16(acc[mt][nt], ah[mt][0], ah[mt][1], ah[mt][2], ah[mt][3], bh0, bh1);
                    mma_f16(acc[mt][nt], ah[mt][0], ah[mt][1], ah[mt][2], ah[mt][3], bl0, bl1);
                }
            }
        }
        __syncthreads();
    }

#pragma unroll
    for (int mt = 0; mt < 2; mt++) {
        int row0 = mBase + wm + mt * 16 + g;
        int row1 = row0 + 8;
#pragma unroll
        for (int nt = 0; nt < 8; nt++) {
            int col = wn + nt * 8 + c2;
            float bx = bk[col], by = bk[col + 1];
            if (row0 < N_NODES) {
                float2 v = make_float2(fmaxf(acc[mt][nt][0] + bx, 0.f),
                                       fmaxf(acc[mt][nt][1] + by, 0.f));
                *(float2*)(out + (size_t)row0 * OUTC + col) = v;
            }
            if (row1 < N_NODES) {
                float2 v = make_float2(fmaxf(acc[mt][nt][2] + bx, 0.f),
                                       fmaxf(acc[mt][nt][3] + by, 0.f));
                *(float2*)(out + (size_t)row1 * OUTC + col) = v;
            }
        }
    }
}

// ---------------- elementwise branch -----------------------------------------
#define EBM 64
#define EBK 32
__global__ void elem_kernel(const float* __restrict__ x,
                            const float* __restrict__ W11,
                            const float* __restrict__ b11,
                            const float* __restrict__ W12,
                            const float* __restrict__ b12,
                            float* __restrict__ out) {
    __shared__ float Xs[EBM][36];
    __shared__ float B1s[EBK][64];
    __shared__ float B2s[EBK][64];
    int tid = threadIdx.x;
    int tx = tid & 15;
    int ty = tid >> 4;
    int mBase = blockIdx.x * EBM;

    float a1[4][4], a2[4][4];
#pragma unroll
    for (int i = 0; i < 4; i++)
#pragma unroll
        for (int j = 0; j < 4; j++) { a1[i][j] = 0.f; a2[i][j] = 0.f; }

    for (int k0 = 0; k0 < NINP; k0 += EBK) {
#pragma unroll
        for (int r = 0; r < 2; r++) {
            int idx = tid + r * 256;
            int m = idx >> 3, qq = idx & 7;
            float4 v = make_float4(0.f, 0.f, 0.f, 0.f);
            if (mBase + m < N_NODES)
                v = *(const float4*)(x + (size_t)(mBase + m) * NINP + k0 + qq * 4);
            *(float4*)&Xs[m][qq * 4] = v;
        }
#pragma unroll
        for (int r = 0; r < 2; r++) {
            int idx = tid + r * 256;
            int kr = idx >> 4, nq = idx & 15;
            *(float4*)&B1s[kr][nq * 4] = *(const float4*)(W11 + (size_t)(k0 + kr) * 64 + nq * 4);
            *(float4*)&B2s[kr][nq * 4] = *(const float4*)(W12 + (size_t)(k0 + kr) * 64 + nq * 4);
        }
        __syncthreads();
#pragma unroll
        for (int k = 0; k < EBK; k++) {
            float av[4];
#pragma unroll
            for (int i = 0; i < 4; i++) av[i] = Xs[ty * 4 + i][k];
            float4 b1 = *(float4*)&B1s[k][tx * 4];
            float4 b2 = *(float4*)&B2s[k][tx * 4];
#pragma unroll
            for (int i = 0; i < 4; i++) {
                a1[i][0] = fmaf(av[i], b1.x, a1[i][0]);
                a1[i][1] = fmaf(av[i], b1.y, a1[i][1]);
                a1[i][2] = fmaf(av[i], b1.z, a1[i][2]);
                a1[i][3] = fmaf(av[i], b1.w, a1[i][3]);
                a2[i][0] = fmaf(av[i], b2.x, a2[i][0]);
                a2[i][1] = fmaf(av[i], b2.y, a2[i][1]);
                a2[i][2] = fmaf(av[i], b2.z, a2[i][2]);
                a2[i][3] = fmaf(av[i], b2.w, a2[i][3]);
            }
        }
        __syncthreads();
    }
    float4 c1 = *(const float4*)(b11 + tx * 4);
    float4 c2 = *(const float4*)(b12 + tx * 4);
#pragma unroll
    for (int i = 0; i < 4; i++) {
        int m = mBase + ty * 4 + i;
        if (m < N_NODES) {
            float4 v;
            v.x = tanh_prod(a1[i][0] + c1.x, a2[i][0] + c2.x);
            v.y = tanh_prod(a1[i][1] + c1.y, a2[i][1] + c2.y);
            v.z = tanh_prod(a1[i][2] + c1.z, a2[i][2] + c2.z);
            v.w = tanh_prod(a1[i][3] + c1.w, a2[i][3] + c2.w);
            *(float4*)(out + (size_t)m * OUTC + NOUT1 + tx * 4) = v;
        }
    }
}

// ---------------- launch: fork/join stream DAG --------------------------------
extern "C" void kernel_launch(void* const* d_in, const int* in_sizes, int n_in,
                              void* d_out, int out_size) {
    const float* x   = (const float*)d_in[0];
    const void*  ei  = d_in[1];
    const float* ea  = (const float*)d_in[2];
    const float* W1  = (const float*)d_in[3];
    const float* W2  = (const float*)d_in[4];
    const float* W3  = (const float*)d_in[5];
    const float* W4  = (const float*)d_in[6];
    const float* Wk  = (const float*)d_in[7];
    const float* bk  = (const float*)d_in[8];
    const float* W11 = (const float*)d_in[9];
    const float* b11 = (const float*)d_in[10];
    const float* W12 = (const float*)d_in[11];
    const float* b12 = (const float*)d_in[12];
    float* out = (float*)d_out;

    static cudaStream_t s1 = nullptr, s2 = nullptr;
    static cudaEvent_t evF, ev1, ev2;
    if (!s1) {
        cudaStreamCreateWithFlags(&s1, cudaStreamNonBlocking);
        cudaStreamCreateWithFlags(&s2, cudaStreamNonBlocking);
        cudaEventCreateWithFlags(&evF, cudaEventDisableTiming);
        cudaEventCreateWithFlags(&ev1, cudaEventDisableTiming);
        cudaEventCreateWithFlags(&ev2, cudaEventDisableTiming);
        cudaFuncSetAttribute(edge_mma_kernel,
                             cudaFuncAttributeMaxDynamicSharedMemorySize, EW_SMEM);
        cudaFuncSetAttribute(spectral_mma_kernel,
                             cudaFuncAttributeMaxDynamicSharedMemorySize, SP_SMEM);
    }

    // fork
    cudaEventRecord(evF, 0);
    cudaStreamWaitEvent(s1, evF, 0);
    cudaStreamWaitEvent(s2, evF, 0);

    // branch s2: edge MLP (independent of CSR build)
    edge_mma_kernel<<<1250, 256, EW_SMEM, s2>>>(ea, W1, W2, W3, W4);
    cudaEventRecord(ev2, s2);

    // branch s1: elementwise output + Wk conversion
    elem_kernel<<<(N_NODES + EBM - 1) / EBM, 256, 0, s1>>>(x, W11, b11, W12, b12, out);
    wk_convert_kernel<<<512, 256, 0, s1>>>(Wk);
    cudaEventRecord(ev1, s1);

    // main branch (default stream): CSR build
    detect_zero_kernel<<<(N_NODES + 255) / 256, 256>>>((const unsigned int*)ei);
    hist_kernel<<<N_EDGES / 256, 256>>>(ei);
    scan_partial_kernel<<<(N_NODES + 1023) / 1024, 1024>>>();
    scan_apply_kernel<<<(N_NODES + 1023) / 1024, 1024>>>();
    scatter_kernel<<<N_EDGES / 256, 256>>>(ei);

    // join: aggregate needs CSR (default) + edge feats (s2)
    cudaStreamWaitEvent(0, ev2, 0);
    aggregate_kernel<<<(N_NODES + 7) / 8, 256>>>(x);

    // join: spectral needs aggregate (default) + Wk conversion (s1)
    cudaStreamWaitEvent(0, ev1, 0);
    spectral_mma_kernel<<<(N_NODES + 127) / 128, 256, SP_SMEM>>>(bk, out);
}

// round 17
// speedup vs baseline: 1.2245x; 1.0745x over previous
#include <cuda_runtime.h>
#include <cuda_bf16.h>
#include <cuda_fp16.h>
#include <math.h>

#define N_NODES 50000
#define N_EDGES 800000
#define NINP 128
#define NE 32
#define KSUP 8
#define NOUT1 128
#define NOUT2 64
#define OUTC 192

// ---------------- device scratch ---------------------------------------------
__device__ float g_e[(size_t)N_EDGES * KSUP];             // edge feats, EDGE order
__device__ int   g_deg[N_NODES];
__device__ int   g_off[N_NODES + 1];
__device__ int   g_cur[N_NODES];
__device__ int2  g_se[N_EDGES];                           // CSR slot -> (src, eid)
__device__ int   g_part[64];
__device__ __half g_Hf[(size_t)(N_NODES + 128) * KSUP * NINP];  // H fp16
__device__ __half g_Wkh[KSUP * NINP * NOUT1];             // TRANSPOSED [n][k], hi
__device__ __half g_Wkl[KSUP * NINP * NOUT1];             // TRANSPOSED [n][k], lo
__device__ int   g_is64;

// ---------------- zero-MUFU exp2 / tanh-product ------------------------------
__device__ __forceinline__ float exp2k(float a) {   // ~= e^{2a}
    float y = fminf(fmaxf(a * 2.885390081777927f, -28.f), 28.f);
    float n = rintf(y);
    float f = y - n;
    float p = 1.3333558e-3f;
    p = fmaf(p, f, 9.6181291e-3f);
    p = fmaf(p, f, 5.5504109e-2f);
    p = fmaf(p, f, 2.4022651e-1f);
    p = fmaf(p, f, 6.9314718e-1f);
    p = fmaf(p, f, 1.0f);
    return __int_as_float(__float_as_int(p) + (((int)n) << 23));
}
__device__ __forceinline__ float tanh_prod(float a, float b) { // tanh(a)*tanh(b)
    float za = exp2k(a), zb = exp2k(b);
    float num = (za - 1.f) * (zb - 1.f);
    float den = (za + 1.f) * (zb + 1.f);
    float r = __int_as_float(0x7EF311C3 - __float_as_int(den));
    r = r * fmaf(-den, r, 2.f);
    r = r * fmaf(-den, r, 2.f);
    return num * r;
}

__device__ __forceinline__ int load_idx(const void* ei, long long pos, int is64) {
    if (is64) return (int)((const long long*)ei)[pos];
    return ((const int*)ei)[pos];
}

// ---------------- cp.async helpers -------------------------------------------
__device__ __forceinline__ void cp16(void* dst_smem, const void* src) {
    unsigned d = (unsigned)__cvta_generic_to_shared(dst_smem);
    asm volatile("cp.async.cg.shared.global [%0], [%1], 16;" :: "r"(d), "l"(src));
}
#define CP_COMMIT() asm volatile("cp.async.commit_group;" ::: "memory")
#define CP_WAIT1()  asm volatile("cp.async.wait_group 1;" ::: "memory")
#define CP_WAIT0()  asm volatile("cp.async.wait_group 0;" ::: "memory")

// ---------------- detect idx dtype + zero deg --------------------------------
__global__ void detect_zero_kernel(const unsigned int* __restrict__ ei) {
    int i = blockIdx.x * blockDim.x + threadIdx.x;
    if (i < N_NODES) g_deg[i] = 0;
    if (blockIdx.x == 0 && threadIdx.x == 0) {
        int is64 = 1;
        for (int k = 0; k < 128; k++)
            if (ei[2 * k + 1] != 0u) { is64 = 0; break; }
        g_is64 = is64;
    }
}

// ---------------- CSR build --------------------------------------------------
__global__ void hist_kernel(const void* __restrict__ ei) {
    int e = blockIdx.x * blockDim.x + threadIdx.x;
    if (e >= N_EDGES) return;
    int dst = load_idx(ei, (long long)N_EDGES + e, g_is64);
    atomicAdd(&g_deg[dst], 1);
}

__global__ void scan_partial_kernel() {
    __shared__ int s[1024];
    int i = blockIdx.x * 1024 + threadIdx.x;
    s[threadIdx.x] = (i < N_NODES) ? g_deg[i] : 0;
    __syncthreads();
    for (int d = 512; d > 0; d >>= 1) {
        if (threadIdx.x < d) s[threadIdx.x] += s[threadIdx.x + d];
        __syncthreads();
    }
    if (threadIdx.x == 0) g_part[blockIdx.x] = s[0];
}

__global__ void scan_apply_kernel() {
    __shared__ int sp[64];
    __shared__ int s[1024];
    int tid = threadIdx.x;
    int nblk = gridDim.x;
    if (tid == 0) {
        int run = 0;
        for (int i = 0; i < nblk; i++) { int t = g_part[i]; sp[i] = run; run += t; }
    }
    __syncthreads();
    int base = sp[blockIdx.x];
    int i = blockIdx.x * 1024 + tid;
    int v = (i < N_NODES) ? g_deg[i] : 0;
    s[tid] = v;
    __syncthreads();
    for (int d = 1; d < 1024; d <<= 1) {
        int t = (tid >= d) ? s[tid - d] : 0;
        __syncthreads();
        s[tid] += t;
        __syncthreads();
    }
    int incl = base + s[tid];
    if (i < N_NODES) { g_off[i + 1] = incl; g_cur[i] = incl - v; }
    if (blockIdx.x == 0 && tid == 0) g_off[0] = 0;
}

__global__ void scatter_kernel(const void* __restrict__ ei) {
    int e = blockIdx.x * blockDim.x + threadIdx.x;
    if (e >= N_EDGES) return;
    int is64 = g_is64;
    int dst = load_idx(ei, (long long)N_EDGES + e, is64);
    int src = load_idx(ei, e, is64);
    int p = atomicAdd(&g_cur[dst], 1);
    g_se[p] = make_int2(src, e);
}

// ---------------- mma helpers -------------------------------------------------
__device__ __forceinline__ void mma_f16(float* d, unsigned a0, unsigned a1,
                                        unsigned a2, unsigned a3,
                                        unsigned b0, unsigned b1) {
    asm volatile(
        "mma.sync.aligned.m16n8k16.row.col.f32.f16.f16.f32 "
        "{%0,%1,%2,%3},{%4,%5,%6,%7},{%8,%9},{%0,%1,%2,%3};"
        : "+f"(d[0]), "+f"(d[1]), "+f"(d[2]), "+f"(d[3])
        : "r"(a0), "r"(a1), "r"(a2), "r"(a3), "r"(b0), "r"(b1));
}

__device__ __forceinline__ unsigned pack_h2(float x, float y) {
    __half2 h = __floats2half2_rn(x, y);
    return *(unsigned*)&h;
}

// ---------------- Wk fp16 hi/lo precompute (TRANSPOSED) ----------------------
__global__ void wk_convert_kernel(const float* __restrict__ Wk) {
    int i = blockIdx.x * 256 + threadIdx.x;   // 131072 total
    int k = i >> 7, n = i & 127;
    float v = Wk[i];
    __half h = __float2half_rn(v);
    g_Wkh[(size_t)n * 1024 + k] = h;
    g_Wkl[(size_t)n * 1024 + k] = __float2half_rn(v - __half2float(h));
}

// ---------------- edge MLP via tensor cores (fp16 A single, B hi/lo) ---------
#define EW_SMEM 35072
#define ECHUNKS 5
__global__ void __launch_bounds__(256, 3) edge_mma_kernel(
        const float* __restrict__ ea, const float* __restrict__ W1,
        const float* __restrict__ W2, const float* __restrict__ W3,
        const float* __restrict__ W4) {
    extern __shared__ char sbuf[];
    __half* Bh  = (__half*)sbuf;             // [192][40]
    __half* Bl  = (__half*)(sbuf + 15360);
    __half* W4h = (__half*)(sbuf + 30720);   // [8 cols][136 k]
    __half* W4l = (__half*)(sbuf + 32896);

    int tid = threadIdx.x;
    int lane = tid & 31, w = tid >> 5;
    int g = lane >> 2, c2 = (lane & 3) * 2;

    // stage weights ONCE (fp16 hi/lo)
    for (int idx = tid; idx < 6144; idx += 256) {
        int n = idx >> 5, k = idx & 31;
        int s = n >> 6, j = n & 63;
        const float* Wp = (s == 0) ? W1 : (s == 1) ? W2 : W3;
        float v = Wp[k * 64 + j];
        __half h = __float2half_rn(v);
        Bh[n * 40 + k] = h;
        Bl[n * 40 + k] = __float2half_rn(v - __half2float(h));
    }
    for (int idx = tid; idx < 1024; idx += 256) {
        int kk = idx >> 3, c = idx & 7;
        float v = W4[idx];
        __half h = __float2half_rn(v);
        W4h[c * 136 + kk] = h;
        W4l[c * 136 + kk] = __float2half_rn(v - __half2float(h));
    }
    __syncthreads();   // the only barrier in the kernel

    int m0 = w * 16 + g;
    for (int ch = 0; ch < ECHUNKS; ch++) {
        long long eBase = ((long long)blockIdx.x * ECHUNKS + ch) * 128;
        const float* ar = ea + (eBase + m0) * NE;

        // A fragments straight from global, fp16 single
        unsigned ah[2][4];
#pragma unroll
        for (int kc = 0; kc < 2; kc++) {
            int kb = kc * 16 + c2;
            float2 v00 = *(const float2*)(ar + kb);
            float2 v10 = *(const float2*)(ar + 8 * NE + kb);
            float2 v01 = *(const float2*)(ar + kb + 8);
            float2 v11 = *(const float2*)(ar + 8 * NE + kb + 8);
            ah[kc][0] = pack_h2(v00.x, v00.y);
            ah[kc][1] = pack_h2(v10.x, v10.y);
            ah[kc][2] = pack_h2(v01.x, v01.y);
            ah[kc][3] = pack_h2(v11.x, v11.y);
        }

        float o[4] = {0.f, 0.f, 0.f, 0.f};
#pragma unroll
        for (int jp = 0; jp < 4; jp++) {
            int ko = jp * 16;
            unsigned linH[4], mulH[4];
#pragma unroll
            for (int sub = 0; sub < 2; sub++) {
                int j = ko + sub * 8;
                float lin[4] = {0.f, 0.f, 0.f, 0.f};
                float t2[4]  = {0.f, 0.f, 0.f, 0.f};
                float t3[4]  = {0.f, 0.f, 0.f, 0.f};
#pragma unroll
                for (int kc = 0; kc < 2; kc++) {
                    int kb = kc * 16 + c2;
                    {
                        int n = j + g;
                        unsigned bh0 = *(unsigned*)&Bh[n * 40 + kb];
                        unsigned bh1 = *(unsigned*)&Bh[n * 40 + kb + 8];
                        unsigned bl0 = *(unsigned*)&Bl[n * 40 + kb];
                        unsigned bl1 = *(unsigned*)&Bl[n * 40 + kb + 8];
                        mma_f16(lin, ah[kc][0], ah[kc][1], ah[kc][2], ah[kc][3], bh0, bh1);
                        mma_f16(lin, ah[kc][0], ah[kc][1], ah[kc][2], ah[kc][3], bl0, bl1);
                    }
                    {
                        int n = 64 + j + g;
                        unsigned bh0 = *(unsigned*)&Bh[n * 40 + kb];
                        unsigned bh1 = *(unsigned*)&Bh[n * 40 + kb + 8];
                        unsigned bl0 = *(unsigned*)&Bl[n * 40 + kb];
                        unsigned bl1 = *(unsigned*)&Bl[n * 40 + kb + 8];
                        mma_f16(t2, ah[kc][0], ah[kc][1], ah[kc][2], ah[kc][3], bh0, bh1);
                        mma_f16(t2, ah[kc][0], ah[kc][1], ah[kc][2], ah[kc][3], bl0, bl1);
                    }
                    {
                        int n = 128 + j + g;
                        unsigned bh0 = *(unsigned*)&Bh[n * 40 + kb];
                        unsigned bh1 = *(unsigned*)&Bh[n * 40 + kb + 8];
                        unsigned bl0 = *(unsigned*)&Bl[n * 40 + kb];
                        unsigned bl1 = *(unsigned*)&Bl[n * 40 + kb + 8];
                        mma_f16(t3, ah[kc][0], ah[kc][1], ah[kc][2], ah[kc][3], bh0, bh1);
                        mma_f16(t3, ah[kc][0], ah[kc][1], ah[kc][2], ah[kc][3], bl0, bl1);
                    }
                }
                float lv0 = fmaxf(lin[0], 0.f), lv1 = fmaxf(lin[1], 0.f);
                float lv2 = fmaxf(lin[2], 0.f), lv3 = fmaxf(lin[3], 0.f);
                float mv0 = tanh_prod(t2[0], t3[0]), mv1 = tanh_prod(t2[1], t3[1]);
                float mv2 = tanh_prod(t2[2], t3[2]), mv3 = tanh_prod(t2[3], t3[3]);
                linH[sub * 2]     = pack_h2(lv0, lv1);
                linH[sub * 2 + 1] = pack_h2(lv2, lv3);
                mulH[sub * 2]     = pack_h2(mv0, mv1);
                mulH[sub * 2 + 1] = pack_h2(mv2, mv3);
            }
            {
                int kb = ko + c2;
                unsigned b0h = *(unsigned*)&W4h[g * 136 + kb];
                unsigned b1h = *(unsigned*)&W4h[g * 136 + kb + 8];
                unsigned b0l = *(unsigned*)&W4l[g * 136 + kb];
                unsigned b1l = *(unsigned*)&W4l[g * 136 + kb + 8];
                mma_f16(o, linH[0], linH[1], linH[2], linH[3], b0h, b1h);
                mma_f16(o, linH[0], linH[1], linH[2], linH[3], b0l, b1l);
            }
            {
                int kb = 64 + ko + c2;
                unsigned b0h = *(unsigned*)&W4h[g * 136 + kb];
                unsigned b1h = *(unsigned*)&W4h[g * 136 + kb + 8];
                unsigned b0l = *(unsigned*)&W4l[g * 136 + kb];
                unsigned b1l = *(unsigned*)&W4l[g * 136 + kb + 8];
                mma_f16(o, mulH[0], mulH[1], mulH[2], mulH[3], b0h, b1h);
                mma_f16(o, mulH[0], mulH[1], mulH[2], mulH[3], b0l, b1l);
            }
        }
        long long e0 = eBase + m0;
        *(float2*)&g_e[e0 * 8 + c2] =
            make_float2(fmaxf(o[0], 0.f), fmaxf(o[1], 0.f));
        *(float2*)&g_e[(e0 + 8) * 8 + c2] =
            make_float2(fmaxf(o[2], 0.f), fmaxf(o[3], 0.f));
    }
}

// ---------------- per-node aggregation (warp per node, fp16 H out) -----------
__global__ void aggregate_kernel(const float* __restrict__ x) {
    int gw = (blockIdx.x * blockDim.x + threadIdx.x) >> 5;
    if (gw >= N_NODES) return;
    int lane = threadIdx.x & 31;
    int c4 = lane * 4;

    float acc[8][4];
#pragma unroll
    for (int k = 0; k < 8; k++)
#pragma unroll
        for (int c = 0; c < 4; c++) acc[k][c] = 0.f;

    int s = g_off[gw], t = g_off[gw + 1];
    int p = s;
    for (; p + 1 < t; p += 2) {
        int2 se0 = g_se[p], se1 = g_se[p + 1];
        float4 xv0 = *(const float4*)(x + (size_t)se0.x * NINP + c4);
        float4 xv1 = *(const float4*)(x + (size_t)se1.x * NINP + c4);
        const float4* ep0 = (const float4*)(g_e + (size_t)se0.y * 8);
        const float4* ep1 = (const float4*)(g_e + (size_t)se1.y * 8);
        float4 a0 = ep0[0], a1 = ep0[1], b0 = ep1[0], b1 = ep1[1];
        float ek0[8] = {a0.x, a0.y, a0.z, a0.w, a1.x, a1.y, a1.z, a1.w};
        float ek1[8] = {b0.x, b0.y, b0.z, b0.w, b1.x, b1.y, b1.z, b1.w};
#pragma unroll
        for (int k = 0; k < 8; k++) {
            acc[k][0] = fmaf(ek0[k], xv0.x, acc[k][0]);
            acc[k][1] = fmaf(ek0[k], xv0.y, acc[k][1]);
            acc[k][2] = fmaf(ek0[k], xv0.z, acc[k][2]);
            acc[k][3] = fmaf(ek0[k], xv0.w, acc[k][3]);
            acc[k][0] = fmaf(ek1[k], xv1.x, acc[k][0]);
            acc[k][1] = fmaf(ek1[k], xv1.y, acc[k][1]);
            acc[k][2] = fmaf(ek1[k], xv1.z, acc[k][2]);
            acc[k][3] = fmaf(ek1[k], xv1.w, acc[k][3]);
        }
    }
    if (p < t) {
        int2 se0 = g_se[p];
        float4 xv0 = *(const float4*)(x + (size_t)se0.x * NINP + c4);
        const float4* ep0 = (const float4*)(g_e + (size_t)se0.y * 8);
        float4 a0 = ep0[0], a1 = ep0[1];
        float ek0[8] = {a0.x, a0.y, a0.z, a0.w, a1.x, a1.y, a1.z, a1.w};
#pragma unroll
        for (int k = 0; k < 8; k++) {
            acc[k][0] = fmaf(ek0[k], xv0.x, acc[k][0]);
            acc[k][1] = fmaf(ek0[k], xv0.y, acc[k][1]);
            acc[k][2] = fmaf(ek0[k], xv0.z, acc[k][2]);
            acc[k][3] = fmaf(ek0[k], xv0.w, acc[k][3]);
        }
    }
    size_t base = (size_t)gw * (KSUP * NINP) + c4;
#pragma unroll
    for (int k = 0; k < 8; k++) {
        unsigned h0 = pack_h2(acc[k][0], acc[k][1]);
        unsigned h1 = pack_h2(acc[k][2], acc[k][3]);
        *(uint2*)&g_Hf[base + k * NINP] = make_uint2(h0, h1);
    }
}

// ---------------- spectral GEMM: fp16 A single, fp16 B hi/lo, 2x mma ---------
#define SP_SMEM 61440
__global__ void __launch_bounds__(256) spectral_mma_kernel(
        const float* __restrict__ bk, float* __restrict__ out) {
    extern __shared__ __half smh[];
    __half* Ah = smh;                 // 2 x 10240 B
    __half* Bh = smh + 10240;
    __half* Bl = smh + 20480;

    int tid  = threadIdx.x;
    int lane = tid & 31;
    int w    = tid >> 5;
    int wm   = (w & 3) * 32;
    int wn   = (w >> 2) * 64;
    int g    = lane >> 2;
    int c2   = (lane & 3) * 2;
    int mBase = blockIdx.x * 128;

    float acc[2][8][4];
#pragma unroll
    for (int mt = 0; mt < 2; mt++)
#pragma unroll
        for (int nt = 0; nt < 8; nt++)
#pragma unroll
            for (int qq = 0; qq < 4; qq++) acc[mt][nt][qq] = 0.f;

    auto stage = [&](int s, int kc) {
        int o = s * 5120;
#pragma unroll
        for (int i = 0; i < 2; i++) {
            int idx = tid + i * 256;
            int row = idx >> 2, q = (idx & 3) * 8;
            size_t ga = (size_t)(mBase + row) * 1024 + kc + q;
            cp16(&Ah[o + row * 40 + q], g_Hf + ga);
            size_t wa = (size_t)row * 1024 + kc + q;   // row = n (transposed Wk)
            cp16(&Bh[o + row * 40 + q], g_Wkh + wa);
            cp16(&Bl[o + row * 40 + q], g_Wkl + wa);
        }
    };

    stage(0, 0);
    CP_COMMIT();

    for (int c = 0; c < 32; c++) {
        int cur = c & 1;
        if (c + 1 < 32) {
            stage((c + 1) & 1, (c + 1) * 32);
            CP_COMMIT();
            CP_WAIT1();
        } else {
            CP_WAIT0();
        }
        __syncthreads();

        int ob = cur * 5120;
#pragma unroll
        for (int ks = 0; ks < 2; ks++) {
            int ko = ks * 16;
            unsigned ah[2][4];
#pragma unroll
            for (int mt = 0; mt < 2; mt++) {
                int r0 = (wm + mt * 16 + g) * 40 + ob + ko + c2;
                ah[mt][0] = *(const unsigned*)&Ah[r0];
                ah[mt][1] = *(const unsigned*)&Ah[r0 + 8 * 40];
                ah[mt][2] = *(const unsigned*)&Ah[r0 + 8];
                ah[mt][3] = *(const unsigned*)&Ah[r0 + 8 * 40 + 8];
            }
#pragma unroll
            for (int nt = 0; nt < 8; nt++) {
                int n0 = (wn + nt * 8 + g) * 40 + ob + ko + c2;
                unsigned bh0 = *(const unsigned*)&Bh[n0];
                unsigned bh1 = *(const unsigned*)&Bh[n0 + 8];
                unsigned bl0 = *(const unsigned*)&Bl[n0];
                unsigned bl1 = *(const unsigned*)&Bl[n0 + 8];
#pragma unroll
                for (int mt = 0; mt < 2; mt++) {
                    mma_f16(acc[mt][nt], ah[mt][0], ah[mt][1], ah[mt][2], ah[mt][3], bh0, bh1);
                    mma_f16(acc[mt][nt], ah[mt][0], ah[mt][1], ah[mt][2], ah[mt][3], bl0, bl1);
                }
            }
        }
        __syncthreads();
    }

#pragma unroll
    for (int mt = 0; mt < 2; mt++) {
        int row0 = mBase + wm + mt * 16 + g;
        int row1 = row0 + 8;
#pragma unroll
        for (int nt = 0; nt < 8; nt++) {
            int col = wn + nt * 8 + c2;
            float bx = bk[col], by = bk[col + 1];
            if (row0 < N_NODES) {
                float2 v = make_float2(fmaxf(acc[mt][nt][0] + bx, 0.f),
                                       fmaxf(acc[mt][nt][1] + by, 0.f));
                *(float2*)(out + (size_t)row0 * OUTC + col) = v;
            }
            if (row1 < N_NODES) {
                float2 v = make_float2(fmaxf(acc[mt][nt][2] + bx, 0.f),
                                       fmaxf(acc[mt][nt][3] + by, 0.f));
                *(float2*)(out + (size_t)row1 * OUTC + col) = v;
            }
        }
    }
}

// ---------------- elementwise branch -----------------------------------------
#define EBM 64
#define EBK 32
__global__ void elem_kernel(const float* __restrict__ x,
                            const float* __restrict__ W11,
                            const float* __restrict__ b11,
                            const float* __restrict__ W12,
                            const float* __restrict__ b12,
                            float* __restrict__ out) {
    __shared__ float Xs[EBM][36];
    __shared__ float B1s[EBK][64];
    __shared__ float B2s[EBK][64];
    int tid = threadIdx.x;
    int tx = tid & 15;
    int ty = tid >> 4;
    int mBase = blockIdx.x * EBM;

    float a1[4][4], a2[4][4];
#pragma unroll
    for (int i = 0; i < 4; i++)
#pragma unroll
        for (int j = 0; j < 4; j++) { a1[i][j] = 0.f; a2[i][j] = 0.f; }

    for (int k0 = 0; k0 < NINP; k0 += EBK) {
#pragma unroll
        for (int r = 0; r < 2; r++) {
            int idx = tid + r * 256;
            int m = idx >> 3, qq = idx & 7;
            float4 v = make_float4(0.f, 0.f, 0.f, 0.f);
            if (mBase + m < N_NODES)
                v = *(const float4*)(x + (size_t)(mBase + m) * NINP + k0 + qq * 4);
            *(float4*)&Xs[m][qq * 4] = v;
        }
#pragma unroll
        for (int r = 0; r < 2; r++) {
            int idx = tid + r * 256;
            int kr = idx >> 4, nq = idx & 15;
            *(float4*)&B1s[kr][nq * 4] = *(const float4*)(W11 + (size_t)(k0 + kr) * 64 + nq * 4);
            *(float4*)&B2s[kr][nq * 4] = *(const float4*)(W12 + (size_t)(k0 + kr) * 64 + nq * 4);
        }
        __syncthreads();
#pragma unroll
        for (int k = 0; k < EBK; k++) {
            float av[4];
#pragma unroll
            for (int i = 0; i < 4; i++) av[i] = Xs[ty * 4 + i][k];
            float4 b1 = *(float4*)&B1s[k][tx * 4];
            float4 b2 = *(float4*)&B2s[k][tx * 4];
#pragma unroll
            for (int i = 0; i < 4; i++) {
                a1[i][0] = fmaf(av[i], b1.x, a1[i][0]);
                a1[i][1] = fmaf(av[i], b1.y, a1[i][1]);
                a1[i][2] = fmaf(av[i], b1.z, a1[i][2]);
                a1[i][3] = fmaf(av[i], b1.w, a1[i][3]);
                a2[i][0] = fmaf(av[i], b2.x, a2[i][0]);
                a2[i][1] = fmaf(av[i], b2.y, a2[i][1]);
                a2[i][2] = fmaf(av[i], b2.z, a2[i][2]);
                a2[i][3] = fmaf(av[i], b2.w, a2[i][3]);
            }
        }
        __syncthreads();
    }
    float4 c1 = *(const float4*)(b11 + tx * 4);
    float4 c2 = *(const float4*)(b12 + tx * 4);
#pragma unroll
    for (int i = 0; i < 4; i++) {
        int m = mBase + ty * 4 + i;
        if (m < N_NODES) {
            float4 v;
            v.x = tanh_prod(a1[i][0] + c1.x, a2[i][0] + c2.x);
            v.y = tanh_prod(a1[i][1] + c1.y, a2[i][1] + c2.y);
            v.z = tanh_prod(a1[i][2] + c1.z, a2[i][2] + c2.z);
            v.w = tanh_prod(a1[i][3] + c1.w, a2[i][3] + c2.w);
            *(float4*)(out + (size_t)m * OUTC + NOUT1 + tx * 4) = v;
        }
    }
}

// ---------------- launch: fork/join stream DAG --------------------------------
extern "C" void kernel_launch(void* const* d_in, const int* in_sizes, int n_in,
                              void* d_out, int out_size) {
    const float* x   = (const float*)d_in[0];
    const void*  ei  = d_in[1];
    const float* ea  = (const float*)d_in[2];
    const float* W1  = (const float*)d_in[3];
    const float* W2  = (const float*)d_in[4];
    const float* W3  = (const float*)d_in[5];
    const float* W4  = (const float*)d_in[6];
    const float* Wk  = (const float*)d_in[7];
    const float* bk  = (const float*)d_in[8];
    const float* W11 = (const float*)d_in[9];
    const float* b11 = (const float*)d_in[10];
    const float* W12 = (const float*)d_in[11];
    const float* b12 = (const float*)d_in[12];
    float* out = (float*)d_out;

    static cudaStream_t s1 = nullptr, s2 = nullptr;
    static cudaEvent_t evF, ev1, ev2;
    if (!s1) {
        cudaStreamCreateWithFlags(&s1, cudaStreamNonBlocking);
        cudaStreamCreateWithFlags(&s2, cudaStreamNonBlocking);
        cudaEventCreateWithFlags(&evF, cudaEventDisableTiming);
        cudaEventCreateWithFlags(&ev1, cudaEventDisableTiming);
        cudaEventCreateWithFlags(&ev2, cudaEventDisableTiming);
        cudaFuncSetAttribute(edge_mma_kernel,
                             cudaFuncAttributeMaxDynamicSharedMemorySize, EW_SMEM);
        cudaFuncSetAttribute(spectral_mma_kernel,
                             cudaFuncAttributeMaxDynamicSharedMemorySize, SP_SMEM);
    }

    // fork
    cudaEventRecord(evF, 0);
    cudaStreamWaitEvent(s1, evF, 0);
    cudaStreamWaitEvent(s2, evF, 0);

    // branch s2: edge MLP (independent of CSR build)
    edge_mma_kernel<<<1250, 256, EW_SMEM, s2>>>(ea, W1, W2, W3, W4);
    cudaEventRecord(ev2, s2);

    // branch s1: elementwise output + Wk conversion
    elem_kernel<<<(N_NODES + EBM - 1) / EBM, 256, 0, s1>>>(x, W11, b11, W12, b12, out);
    wk_convert_kernel<<<512, 256, 0, s1>>>(Wk);
    cudaEventRecord(ev1, s1);

    // main branch (default stream): CSR build
    detect_zero_kernel<<<(N_NODES + 255) / 256, 256>>>((const unsigned int*)ei);
    hist_kernel<<<N_EDGES / 256, 256>>>(ei);
    scan_partial_kernel<<<(N_NODES + 1023) / 1024, 1024>>>();
    scan_apply_kernel<<<(N_NODES + 1023) / 1024, 1024>>>();
    scatter_kernel<<<N_EDGES / 256, 256>>>(ei);

    // join: aggregate needs CSR (default) + edge feats (s2)
    cudaStreamWaitEvent(0, ev2, 0);
    aggregate_kernel<<<(N_NODES + 7) / 8, 256>>>(x);

    // join: spectral needs aggregate (default) + Wk conversion (s1)
    cudaStreamWaitEvent(0, ev1, 0);
    spectral_mma_kernel<<<(N_NODES + 127) / 128, 256, SP_SMEM>>>(bk, out);
}